// round 5
// baseline (speedup 1.0000x reference)
#include <cuda_runtime.h>

#define B_TOTAL 131072
#define T_STEPS 8
#define NB 8
#define WARPS 16
#define THREADS (WARPS * 32)
#define BPB (NB * WARPS)           // 128 batches per block
#define NBLK (B_TOTAL / BPB)       // 1024 blocks

// Layer-1 output scratch, layout [blk][warp][t][k(64)][nb(8)] = 256 MB
__device__ float g_h1[(size_t)NBLK * WARPS * T_STEPS * 64 * NB];

typedef unsigned long long u64t;

__device__ __forceinline__ u64t pk(float x, float y) {
    u64t r; asm("mov.b64 %0, {%1, %2};" : "=l"(r) : "f"(x), "f"(y)); return r;
}
__device__ __forceinline__ void upk(u64t v, float& x, float& y) {
    asm("mov.b64 {%0, %1}, %2;" : "=f"(x), "=f"(y) : "l"(v));
}
__device__ __forceinline__ void fma2(u64t& d, u64t a, u64t b) {
    asm("fma.rn.f32x2 %0, %1, %2, %0;" : "+l"(d) : "l"(a), "l"(b));
}

__device__ __forceinline__ float tanha(float x) {
    float r; asm("tanh.approx.f32 %0, %1;" : "=f"(r) : "f"(x)); return r;
}
__device__ __forceinline__ float sigf(float x) {
    return fmaf(tanha(0.5f * x), 0.5f, 0.5f);
}

// smem float counts
// pass1: sWih 1536 | sWhh 16384 | sBias 256 | sH[16][64][8]=8192 | sX[16][48][8]=6144 -> 32512 (130048 B)
// pass2: sW 32768 | sBias 256 | sIn[16][128][8]=16384 -> 49408 (197632 B)
#define SMEM1_BYTES (32512 * 4)
#define SMEM2_BYTES (49408 * 4)

// one k-slice of the gate GEMM: weights per-lane (2x float4), inputs broadcast (2x float4)
#define K_SLICE(W4PTR, H4PTR, KW, KH)                                          \
    {                                                                           \
        float4 wa = (W4PTR)[(KW) * 64 + lane];                                  \
        float4 wb = (W4PTR)[(KW) * 64 + lane + 32];                             \
        float4 hA = (H4PTR)[(KH) * 2];                                          \
        float4 hB = (H4PTR)[(KH) * 2 + 1];                                      \
        u64t wif1 = pk(wa.x, wa.y), wgo1 = pk(wa.z, wa.w);                      \
        u64t wif2 = pk(wb.x, wb.y), wgo2 = pk(wb.z, wb.w);                      \
        float hv[8] = {hA.x, hA.y, hA.z, hA.w, hB.x, hB.y, hB.z, hB.w};         \
        _Pragma("unroll")                                                       \
        for (int nb = 0; nb < NB; nb++) {                                       \
            u64t vv = pk(hv[nb], hv[nb]);                                       \
            fma2(aif1[nb], vv, wif1);                                           \
            fma2(ago1[nb], vv, wgo1);                                           \
            fma2(aif2[nb], vv, wif2);                                           \
            fma2(ago2[nb], vv, wgo2);                                           \
        }                                                                       \
    }

#define ACT_AND_STATE(nb)                                                       \
    float ha_##nb, hb_##nb;                                                     \
    {                                                                           \
        float gi, gf, gg, go;                                                   \
        upk(aif1[nb], gi, gf); upk(ago1[nb], gg, go);                           \
        float i1 = sigf(gi), f1 = sigf(gf), g1 = tanha(gg), o1 = sigf(go);      \
        ca[nb] = f1 * ca[nb] + i1 * g1;                                         \
        ha_##nb = o1 * tanha(ca[nb]);                                           \
        upk(aif2[nb], gi, gf); upk(ago2[nb], gg, go);                           \
        float i2 = sigf(gi), f2 = sigf(gf), g2 = tanha(gg), o2 = sigf(go);      \
        cb[nb] = f2 * cb[nb] + i2 * g2;                                         \
        hb_##nb = o2 * tanha(cb[nb]);                                           \
    }

__global__ void __launch_bounds__(THREADS) lstm_pass1(
    const float* __restrict__ x,
    const float* __restrict__ Wih, const float* __restrict__ Whh,
    const float* __restrict__ bih, const float* __restrict__ bhh)
{
    extern __shared__ float sm[];
    float* sWih  = sm;                 // [i(6)][j(64)][gate(4)]
    float* sWhh  = sWih + 1536;        // [k(64)][j(64)][gate(4)]
    float* sBias = sWhh + 16384;       // [j(64)][gate(4)]
    float* sH    = sBias + 256;        // [w(16)][k(64)][nb(8)]
    float* sX    = sH + WARPS * 512;   // [w(16)][t*6+i(48)][nb(8)]

    const int tid = threadIdx.x;

    for (int idx = tid; idx < 1536; idx += THREADS) {
        int r = idx / 6, i = idx - r * 6;
        int gate = r >> 6, j = r & 63;
        sWih[(i * 64 + j) * 4 + gate] = Wih[idx];
    }
    for (int idx = tid; idx < 16384; idx += THREADS) {
        int r = idx >> 6, k = idx & 63;
        int gate = r >> 6, j = r & 63;
        sWhh[(k * 64 + j) * 4 + gate] = Whh[idx];
    }
    if (tid < 256) {
        int gate = tid >> 6, j = tid & 63;
        sBias[j * 4 + gate] = bih[tid] + bhh[tid];
    }
    for (int idx = tid; idx < WARPS * 512; idx += THREADS) sH[idx] = 0.0f;

    const int base = blockIdx.x * BPB;
    for (int idx = tid; idx < BPB * 48; idx += THREADS) {
        int nbl = idx / 48, rem = idx - nbl * 48;     // nbl = w*8+nb, rem = t*6+i
        int wq = nbl >> 3, nb = nbl & 7;
        sX[wq * 384 + rem * 8 + nb] = x[(base + nbl) * 48 + rem];
    }
    __syncthreads();

    const int w = tid >> 5, lane = tid & 31;
    const float4* W4  = (const float4*)sWhh;
    const float4* Wx4 = (const float4*)sWih;
    const float4* H4  = (const float4*)(sH + w * 512);   // [k][nb8] as 2 float4 per k
    const float4* X4  = (const float4*)(sX + w * 384);   // [rem][nb8] as 2 float4 per rem
    const float4  bj  = ((const float4*)sBias)[lane];
    const float4  bj2 = ((const float4*)sBias)[lane + 32];
    const u64t b_if1 = pk(bj.x, bj.y),  b_go1 = pk(bj.z, bj.w);
    const u64t b_if2 = pk(bj2.x, bj2.y), b_go2 = pk(bj2.z, bj2.w);

    float ca[NB], cb[NB];
#pragma unroll
    for (int nb = 0; nb < NB; nb++) { ca[nb] = cb[nb] = 0.0f; }

    float* gdst = g_h1 + ((size_t)blockIdx.x * WARPS + w) * T_STEPS * 512;

    for (int t = 0; t < T_STEPS; t++) {
        u64t aif1[NB], ago1[NB], aif2[NB], ago2[NB];
#pragma unroll
        for (int nb = 0; nb < NB; nb++) {
            aif1[nb] = b_if1; ago1[nb] = b_go1;
            aif2[nb] = b_if2; ago2[nb] = b_go2;
        }

#pragma unroll
        for (int i = 0; i < 6; i++) K_SLICE(Wx4, X4, i, t * 6 + i);

#pragma unroll 8
        for (int k = 0; k < 64; k++) K_SLICE(W4, H4, k, k);

        __syncwarp();
        float* hrow1 = sH + w * 512 + lane * 8;
        float* hrow2 = sH + w * 512 + (lane + 32) * 8;
        float* grow1 = gdst + t * 512 + lane * 8;
        float* grow2 = gdst + t * 512 + (lane + 32) * 8;
        {
            ACT_AND_STATE(0); ACT_AND_STATE(1); ACT_AND_STATE(2); ACT_AND_STATE(3);
            ACT_AND_STATE(4); ACT_AND_STATE(5); ACT_AND_STATE(6); ACT_AND_STATE(7);
            float4 va0 = {ha_0, ha_1, ha_2, ha_3}, va1 = {ha_4, ha_5, ha_6, ha_7};
            float4 vb0 = {hb_0, hb_1, hb_2, hb_3}, vb1 = {hb_4, hb_5, hb_6, hb_7};
            ((float4*)hrow1)[0] = va0; ((float4*)hrow1)[1] = va1;
            ((float4*)hrow2)[0] = vb0; ((float4*)hrow2)[1] = vb1;
            ((float4*)grow1)[0] = va0; ((float4*)grow1)[1] = va1;
            ((float4*)grow2)[0] = vb0; ((float4*)grow2)[1] = vb1;
        }
        __syncwarp();
    }
}

__global__ void __launch_bounds__(THREADS) lstm_pass2(
    const float* __restrict__ Wih, const float* __restrict__ Whh,
    const float* __restrict__ bih, const float* __restrict__ bhh,
    const float* __restrict__ Wfc, const float* __restrict__ bfc,
    float* __restrict__ out)
{
    extern __shared__ float sm[];
    float* sW    = sm;            // [kk(128)][j(64)][gate(4)]  kk<64: Wih1, kk>=64: Whh1
    float* sBias = sW + 32768;    // [j(64)][gate(4)]
    float* sIn   = sBias + 256;   // [w(16)][kk(128)][nb(8)]  kk<64: layer1 h, kk>=64: layer2 h

    const int tid = threadIdx.x;

    for (int idx = tid; idx < 16384; idx += THREADS) {
        int r = idx >> 6, k = idx & 63;
        int gate = r >> 6, j = r & 63;
        sW[(k * 64 + j) * 4 + gate]        = Wih[idx];
        sW[((k + 64) * 64 + j) * 4 + gate] = Whh[idx];
    }
    if (tid < 256) {
        int gate = tid >> 6, j = tid & 63;
        sBias[j * 4 + gate] = bih[tid] + bhh[tid];
    }
    for (int idx = tid; idx < WARPS * 1024; idx += THREADS) sIn[idx] = 0.0f;
    __syncthreads();

    const int w = tid >> 5, lane = tid & 31;
    const float4* W4 = (const float4*)sW;
    const float4* H4 = (const float4*)(sIn + w * 1024);  // [kk][nb8]
    const float4  bj  = ((const float4*)sBias)[lane];
    const float4  bj2 = ((const float4*)sBias)[lane + 32];
    const u64t b_if1 = pk(bj.x, bj.y),  b_go1 = pk(bj.z, bj.w);
    const u64t b_if2 = pk(bj2.x, bj2.y), b_go2 = pk(bj2.z, bj2.w);
    const float wf1 = Wfc[lane];
    const float wf2 = Wfc[lane + 32];

    float ca[NB], cb[NB];
#pragma unroll
    for (int nb = 0; nb < NB; nb++) { ca[nb] = cb[nb] = 0.0f; }

    const float* gsrc = g_h1 + ((size_t)blockIdx.x * WARPS + w) * T_STEPS * 512;

    float pacc[NB];
#pragma unroll
    for (int nb = 0; nb < NB; nb++) pacc[nb] = 0.0f;

    for (int t = 0; t < T_STEPS; t++) {
        // stage layer-1 h for this step: straight 512-float copy, coalesced
        {
            const float4* src4 = (const float4*)(gsrc + t * 512);
            float4* dst4 = (float4*)(sIn + w * 1024);
#pragma unroll
            for (int q = 0; q < 4; q++) dst4[lane + q * 32] = src4[lane + q * 32];
        }
        __syncwarp();

        u64t aif1[NB], ago1[NB], aif2[NB], ago2[NB];
#pragma unroll
        for (int nb = 0; nb < NB; nb++) {
            aif1[nb] = b_if1; ago1[nb] = b_go1;
            aif2[nb] = b_if2; ago2[nb] = b_go2;
        }

#pragma unroll 8
        for (int k = 0; k < 128; k++) K_SLICE(W4, H4, k, k);

        __syncwarp();
        float* hrow1 = sIn + w * 1024 + (64 + lane) * 8;
        float* hrow2 = sIn + w * 1024 + (64 + lane + 32) * 8;
        {
            ACT_AND_STATE(0); ACT_AND_STATE(1); ACT_AND_STATE(2); ACT_AND_STATE(3);
            ACT_AND_STATE(4); ACT_AND_STATE(5); ACT_AND_STATE(6); ACT_AND_STATE(7);
            float4 va0 = {ha_0, ha_1, ha_2, ha_3}, va1 = {ha_4, ha_5, ha_6, ha_7};
            float4 vb0 = {hb_0, hb_1, hb_2, hb_3}, vb1 = {hb_4, hb_5, hb_6, hb_7};
            ((float4*)hrow1)[0] = va0; ((float4*)hrow1)[1] = va1;
            ((float4*)hrow2)[0] = vb0; ((float4*)hrow2)[1] = vb1;
            if (t == T_STEPS - 1) {
                float ha_arr[8] = {ha_0, ha_1, ha_2, ha_3, ha_4, ha_5, ha_6, ha_7};
                float hb_arr[8] = {hb_0, hb_1, hb_2, hb_3, hb_4, hb_5, hb_6, hb_7};
#pragma unroll
                for (int nb = 0; nb < NB; nb++)
                    pacc[nb] = ha_arr[nb] * wf1 + hb_arr[nb] * wf2;
            }
        }
        __syncwarp();
    }

    // fused FC reduction across lanes (j dimension)
#pragma unroll
    for (int off = 16; off >= 1; off >>= 1) {
#pragma unroll
        for (int nb = 0; nb < NB; nb++)
            pacc[nb] += __shfl_xor_sync(0xffffffffu, pacc[nb], off);
    }
    if (lane == 0) {
        const int base = blockIdx.x * BPB + w * NB;
        float b0 = bfc[0];
#pragma unroll
        for (int nb = 0; nb < NB; nb++) out[base + nb] = pacc[nb] + b0;
    }
}

extern "C" void kernel_launch(void* const* d_in, const int* in_sizes, int n_in,
                              void* d_out, int out_size)
{
    const float* x    = (const float*)d_in[0];
    const float* Wih0 = (const float*)d_in[1];
    const float* Whh0 = (const float*)d_in[2];
    const float* bih0 = (const float*)d_in[3];
    const float* bhh0 = (const float*)d_in[4];
    const float* Wih1 = (const float*)d_in[5];
    const float* Whh1 = (const float*)d_in[6];
    const float* bih1 = (const float*)d_in[7];
    const float* bhh1 = (const float*)d_in[8];
    const float* Wfc  = (const float*)d_in[9];
    const float* bfc  = (const float*)d_in[10];
    float* out = (float*)d_out;

    cudaFuncSetAttribute(lstm_pass1, cudaFuncAttributeMaxDynamicSharedMemorySize, SMEM1_BYTES);
    cudaFuncSetAttribute(lstm_pass2, cudaFuncAttributeMaxDynamicSharedMemorySize, SMEM2_BYTES);

    lstm_pass1<<<NBLK, THREADS, SMEM1_BYTES>>>(x, Wih0, Whh0, bih0, bhh0);
    lstm_pass2<<<NBLK, THREADS, SMEM2_BYTES>>>(Wih1, Whh1, bih1, bhh1, Wfc, bfc, out);
}

// round 7
// speedup vs baseline: 1.8969x; 1.8969x over previous
#include <cuda_runtime.h>
#include <cuda_bf16.h>
#include <cstdint>
#include <cstring>

#define T_STEPS 8
#define NBLK 1024
#define THREADS 256

// layer-1 h sequence, packed (bf16 hi | bf16 lo) u32: [blk][t][m(128)][j(64)]
__device__ uint32_t g_h1[(size_t)NBLK * T_STEPS * 8192];

// ---------------- kernel1 smem layout (bytes) ----------------
#define K1_BX    0         // [256][40] bf16 (80B rows): x-weights folded
#define K1_W1H   20480     // Whh0 hi [256][72] (144B rows)
#define K1_W1L   57344
#define K1_XT    94208     // x A-tile [128][40]
#define K1_H1H   104448    // h1 hi [128][72]
#define K1_H1L   122880
#define K1_BIAS  141312    // fp32 [256]
#define K1_SMEM  142336

// ---------------- kernel2 smem layout ----------------
#define K2_W2H   0         // [Wih1|Whh1] hi [256][136] (272B rows)
#define K2_W2L   69632
#define K2_H1H   139264    // h1 hi [128][72]
#define K2_H1L   157696
#define K2_H2H   176128
#define K2_H2L   194560
#define K2_BIAS  212992
#define K2_WFC   214016    // fp32 [64]
#define K2_SCR   214272    // fp32 [128] FC scratch
#define K2_SMEM  214784

__device__ __forceinline__ uint32_t smem_u32(const void* p) {
    uint32_t a;
    asm("{ .reg .u64 t; cvta.to.shared.u64 t, %1; cvt.u32.u64 %0, t; }" : "=r"(a) : "l"(p));
    return a;
}
__device__ __forceinline__ void mma16816(float* d, const uint32_t* a, const uint32_t* b) {
    asm volatile("mma.sync.aligned.m16n8k16.row.col.f32.bf16.bf16.f32 "
        "{%0,%1,%2,%3},{%4,%5,%6,%7},{%8,%9},{%0,%1,%2,%3};"
        : "+f"(d[0]), "+f"(d[1]), "+f"(d[2]), "+f"(d[3])
        : "r"(a[0]), "r"(a[1]), "r"(a[2]), "r"(a[3]), "r"(b[0]), "r"(b[1]));
}
__device__ __forceinline__ void ldsm_x4(uint32_t* r, uint32_t addr) {
    asm volatile("ldmatrix.sync.aligned.m8n8.x4.shared.b16 {%0,%1,%2,%3}, [%4];"
        : "=r"(r[0]), "=r"(r[1]), "=r"(r[2]), "=r"(r[3]) : "r"(addr));
}
__device__ __forceinline__ void ldsm_x2(uint32_t* r, uint32_t addr) {
    asm volatile("ldmatrix.sync.aligned.m8n8.x2.shared.b16 {%0,%1}, [%2];"
        : "=r"(r[0]), "=r"(r[1]) : "r"(addr));
}
__device__ __forceinline__ float tanha(float x) {
    float r; asm("tanh.approx.f32 %0, %1;" : "=f"(r) : "f"(x)); return r;
}
__device__ __forceinline__ float sigf(float x) { return fmaf(tanha(0.5f * x), 0.5f, 0.5f); }

__device__ __forceinline__ void split_bf16(float v, __nv_bfloat16& hi, __nv_bfloat16& lo) {
    hi = __float2bfloat16(v);
    lo = __float2bfloat16(v - __bfloat162float(hi));
}

// ============================ kernel 1: layer 1 ============================
__global__ void __launch_bounds__(THREADS, 1) lstm_l1(
    const float* __restrict__ x,
    const float* __restrict__ Wih0, const float* __restrict__ Whh0,
    const float* __restrict__ bih0, const float* __restrict__ bhh0)
{
    extern __shared__ char sm[];
    const int tid = threadIdx.x;

    for (int i = tid; i < K1_SMEM / 4; i += THREADS) ((uint32_t*)sm)[i] = 0;
    __syncthreads();

    for (int idx = tid; idx < 1536; idx += THREADS) {
        int r = idx / 6, i = idx - r * 6;
        __nv_bfloat16 hi, lo; split_bf16(Wih0[idx], hi, lo);
        *(__nv_bfloat16*)(sm + K1_BX + r * 80 + i * 2) = hi;       // vs xhi
        *(__nv_bfloat16*)(sm + K1_BX + r * 80 + (8 + i) * 2) = hi; // vs xlo
        *(__nv_bfloat16*)(sm + K1_BX + r * 80 + (16 + i) * 2) = lo;// vs xhi
    }
    for (int idx = tid; idx < 16384; idx += THREADS) {
        int r = idx >> 6, k = idx & 63;
        __nv_bfloat16 hi, lo; split_bf16(Whh0[idx], hi, lo);
        *(__nv_bfloat16*)(sm + K1_W1H + r * 144 + k * 2) = hi;
        *(__nv_bfloat16*)(sm + K1_W1L + r * 144 + k * 2) = lo;
    }
    if (tid < 256) ((float*)(sm + K1_BIAS))[tid] = bih0[tid] + bhh0[tid];
    __syncthreads();

    const int l = tid & 31, w = tid >> 5, mw = w >> 2, nw = w & 3;
    const int m0 = mw * 64;
    const uint32_t sb = smem_u32(sm);
    const int rowA = l & 15;
    const int colA = (l & 16) ? 16 : 0;   // +8 bf16 cols
    const int rowBn = l & 7;
    const int colB = (l & 8) ? 16 : 0;
    const size_t gb = (size_t)blockIdx.x * 128;
    const float* biasp = (const float*)(sm + K1_BIAS);

    float c[32], hreg[32];
#pragma unroll
    for (int i = 0; i < 32; i++) { c[i] = 0.0f; hreg[i] = 0.0f; }

    for (int t = 0; t < T_STEPS; t++) {
        // ---- phase A: write h(t-1) tiles, stage x(t) ----
        if (t > 0) {
#pragma unroll
            for (int p = 0; p < 2; p++)
#pragma unroll
            for (int mt = 0; mt < 4; mt++)
#pragma unroll
            for (int rr = 0; rr < 2; rr++)
#pragma unroll
            for (int jj = 0; jj < 2; jj++) {
                int r = m0 + 16 * mt + (l >> 2) + 8 * rr;
                int j = nw * 16 + p * 8 + 2 * (l & 3) + jj;
                __nv_bfloat16 hi, lo;
                split_bf16(hreg[((p * 4 + mt) * 2 + rr) * 2 + jj], hi, lo);
                *(__nv_bfloat16*)(sm + K1_H1H + r * 144 + j * 2) = hi;
                *(__nv_bfloat16*)(sm + K1_H1L + r * 144 + j * 2) = lo;
            }
        }
        if (tid < 128) {
            const float* xr = x + (gb + tid) * 48 + t * 6;
            char* xrow = sm + K1_XT + tid * 80;
#pragma unroll
            for (int i = 0; i < 6; i++) {
                __nv_bfloat16 hi, lo; split_bf16(xr[i], hi, lo);
                *(__nv_bfloat16*)(xrow + i * 2) = hi;
                *(__nv_bfloat16*)(xrow + (8 + i) * 2) = lo;
                *(__nv_bfloat16*)(xrow + (16 + i) * 2) = hi;
            }
        }
        __syncthreads();

        // ---- phase B: pack h(t-1) to gmem; MMA; epilogue ----
        if (t > 0) {
            uint32_t* gdst = g_h1 + ((size_t)blockIdx.x * T_STEPS + (t - 1)) * 8192;
#pragma unroll
            for (int q = 0; q < 8; q++) {
                int idx = q * 1024 + tid * 4;
                int m = idx >> 6, j = idx & 63;
                uint2 hv = *(uint2*)(sm + K1_H1H + m * 144 + j * 2);
                uint2 lv = *(uint2*)(sm + K1_H1L + m * 144 + j * 2);
                uint4 o;
                o.x = __byte_perm(hv.x, lv.x, 0x5410);
                o.y = __byte_perm(hv.x, lv.x, 0x7632);
                o.z = __byte_perm(hv.y, lv.y, 0x5410);
                o.w = __byte_perm(hv.y, lv.y, 0x7632);
                *(uint4*)(gdst + idx) = o;
            }
        }

#pragma unroll
        for (int p = 0; p < 2; p++) {
            const int js = nw * 16 + p * 8;
            float d[4][4][4];
#pragma unroll
            for (int g = 0; g < 4; g++) {
                float b0 = biasp[g * 64 + js + 2 * (l & 3)];
                float b1 = biasp[g * 64 + js + 2 * (l & 3) + 1];
#pragma unroll
                for (int mt = 0; mt < 4; mt++) {
                    d[mt][g][0] = b0; d[mt][g][1] = b1;
                    d[mt][g][2] = b0; d[mt][g][3] = b1;
                }
            }
            // x-part (K=32 folded tile)
#pragma unroll
            for (int kt = 0; kt < 2; kt++) {
                int k0 = kt * 16;
                uint32_t bx[4][2];
#pragma unroll
                for (int g = 0; g < 4; g++)
                    ldsm_x2(bx[g], sb + K1_BX + (uint32_t)(g * 64 + js + rowBn) * 80 + k0 * 2 + colB);
#pragma unroll
                for (int mt = 0; mt < 4; mt++) {
                    uint32_t a[4];
                    ldsm_x4(a, sb + K1_XT + (uint32_t)(m0 + 16 * mt + rowA) * 80 + k0 * 2 + colA);
#pragma unroll
                    for (int g = 0; g < 4; g++) mma16816(d[mt][g], a, bx[g]);
                }
            }
            // h-part: 3-term split over K=64
#pragma unroll
            for (int kt = 0; kt < 4; kt++) {
                int k0 = kt * 16;
                uint32_t bh[4][2], bl[4][2];
#pragma unroll
                for (int g = 0; g < 4; g++) {
                    ldsm_x2(bh[g], sb + K1_W1H + (uint32_t)(g * 64 + js + rowBn) * 144 + k0 * 2 + colB);
                    ldsm_x2(bl[g], sb + K1_W1L + (uint32_t)(g * 64 + js + rowBn) * 144 + k0 * 2 + colB);
                }
#pragma unroll
                for (int mt = 0; mt < 4; mt++) {
                    uint32_t ah[4], al[4];
                    ldsm_x4(ah, sb + K1_H1H + (uint32_t)(m0 + 16 * mt + rowA) * 144 + k0 * 2 + colA);
                    ldsm_x4(al, sb + K1_H1L + (uint32_t)(m0 + 16 * mt + rowA) * 144 + k0 * 2 + colA);
#pragma unroll
                    for (int g = 0; g < 4; g++) {
                        mma16816(d[mt][g], ah, bh[g]);
                        mma16816(d[mt][g], al, bh[g]);
                        mma16816(d[mt][g], ah, bl[g]);
                    }
                }
            }
            // epilogue -> registers
#pragma unroll
            for (int mt = 0; mt < 4; mt++)
#pragma unroll
            for (int rr = 0; rr < 2; rr++)
#pragma unroll
            for (int jj = 0; jj < 2; jj++) {
                int reg = rr * 2 + jj;
                float gi = d[mt][0][reg], gf = d[mt][1][reg];
                float gg = d[mt][2][reg], go = d[mt][3][reg];
                int ci = ((p * 4 + mt) * 2 + rr) * 2 + jj;
                float cc = sigf(gf) * c[ci] + sigf(gi) * tanha(gg);
                c[ci] = cc;
                hreg[ci] = sigf(go) * tanha(cc);
            }
        }
        __syncthreads();
    }

    // final h(7): write tiles then pack
#pragma unroll
    for (int p = 0; p < 2; p++)
#pragma unroll
    for (int mt = 0; mt < 4; mt++)
#pragma unroll
    for (int rr = 0; rr < 2; rr++)
#pragma unroll
    for (int jj = 0; jj < 2; jj++) {
        int r = m0 + 16 * mt + (l >> 2) + 8 * rr;
        int j = nw * 16 + p * 8 + 2 * (l & 3) + jj;
        __nv_bfloat16 hi, lo;
        split_bf16(hreg[((p * 4 + mt) * 2 + rr) * 2 + jj], hi, lo);
        *(__nv_bfloat16*)(sm + K1_H1H + r * 144 + j * 2) = hi;
        *(__nv_bfloat16*)(sm + K1_H1L + r * 144 + j * 2) = lo;
    }
    __syncthreads();
    {
        uint32_t* gdst = g_h1 + ((size_t)blockIdx.x * T_STEPS + 7) * 8192;
#pragma unroll
        for (int q = 0; q < 8; q++) {
            int idx = q * 1024 + tid * 4;
            int m = idx >> 6, j = idx & 63;
            uint2 hv = *(uint2*)(sm + K1_H1H + m * 144 + j * 2);
            uint2 lv = *(uint2*)(sm + K1_H1L + m * 144 + j * 2);
            uint4 o;
            o.x = __byte_perm(hv.x, lv.x, 0x5410);
            o.y = __byte_perm(hv.x, lv.x, 0x7632);
            o.z = __byte_perm(hv.y, lv.y, 0x5410);
            o.w = __byte_perm(hv.y, lv.y, 0x7632);
            *(uint4*)(gdst + idx) = o;
        }
    }
}

// ============================ kernel 2: layer 2 + FC ============================
__global__ void __launch_bounds__(THREADS, 1) lstm_l2(
    const float* __restrict__ Wih1, const float* __restrict__ Whh1,
    const float* __restrict__ bih1, const float* __restrict__ bhh1,
    const float* __restrict__ Wfc, const float* __restrict__ bfc,
    float* __restrict__ out)
{
    extern __shared__ char sm[];
    const int tid = threadIdx.x;

    for (int i = tid; i < K2_SMEM / 4; i += THREADS) ((uint32_t*)sm)[i] = 0;
    __syncthreads();

    for (int idx = tid; idx < 16384; idx += THREADS) {
        int r = idx >> 6, k = idx & 63;
        __nv_bfloat16 hi, lo;
        split_bf16(Wih1[idx], hi, lo);
        *(__nv_bfloat16*)(sm + K2_W2H + r * 272 + k * 2) = hi;
        *(__nv_bfloat16*)(sm + K2_W2L + r * 272 + k * 2) = lo;
        split_bf16(Whh1[idx], hi, lo);
        *(__nv_bfloat16*)(sm + K2_W2H + r * 272 + (64 + k) * 2) = hi;
        *(__nv_bfloat16*)(sm + K2_W2L + r * 272 + (64 + k) * 2) = lo;
    }
    if (tid < 256) ((float*)(sm + K2_BIAS))[tid] = bih1[tid] + bhh1[tid];
    if (tid < 64)  ((float*)(sm + K2_WFC))[tid] = Wfc[tid];
    __syncthreads();

    const int l = tid & 31, w = tid >> 5, mw = w >> 2, nw = w & 3;
    const int m0 = mw * 64;
    const uint32_t sb = smem_u32(sm);
    const int rowA = l & 15;
    const int colA = (l & 16) ? 16 : 0;
    const int rowBn = l & 7;
    const int colB = (l & 8) ? 16 : 0;
    const size_t gb = (size_t)blockIdx.x * 128;
    const float* biasp = (const float*)(sm + K2_BIAS);
    const float* wfcp  = (const float*)(sm + K2_WFC);
    float* scr = (float*)(sm + K2_SCR);

    float c[32], hreg[32];
#pragma unroll
    for (int i = 0; i < 32; i++) { c[i] = 0.0f; hreg[i] = 0.0f; }

    for (int t = 0; t < T_STEPS; t++) {
        // ---- phase A: write h2(t-1) tiles, stage h1(t) ----
        if (t > 0) {
#pragma unroll
            for (int p = 0; p < 2; p++)
#pragma unroll
            for (int mt = 0; mt < 4; mt++)
#pragma unroll
            for (int rr = 0; rr < 2; rr++)
#pragma unroll
            for (int jj = 0; jj < 2; jj++) {
                int r = m0 + 16 * mt + (l >> 2) + 8 * rr;
                int j = nw * 16 + p * 8 + 2 * (l & 3) + jj;
                __nv_bfloat16 hi, lo;
                split_bf16(hreg[((p * 4 + mt) * 2 + rr) * 2 + jj], hi, lo);
                *(__nv_bfloat16*)(sm + K2_H2H + r * 144 + j * 2) = hi;
                *(__nv_bfloat16*)(sm + K2_H2L + r * 144 + j * 2) = lo;
            }
        }
        {
            const uint32_t* gsrc = g_h1 + ((size_t)blockIdx.x * T_STEPS + t) * 8192;
#pragma unroll
            for (int q = 0; q < 8; q++) {
                int idx = q * 1024 + tid * 4;
                int m = idx >> 6, j = idx & 63;
                uint4 v = *(const uint4*)(gsrc + idx);
                uint2 hv, lv;
                hv.x = __byte_perm(v.x, v.y, 0x5410);
                lv.x = __byte_perm(v.x, v.y, 0x7632);
                hv.y = __byte_perm(v.z, v.w, 0x5410);
                lv.y = __byte_perm(v.z, v.w, 0x7632);
                *(uint2*)(sm + K2_H1H + m * 144 + j * 2) = hv;
                *(uint2*)(sm + K2_H1L + m * 144 + j * 2) = lv;
            }
        }
        __syncthreads();

        // ---- phase B: MMA + epilogue ----
#pragma unroll
        for (int p = 0; p < 2; p++) {
            const int js = nw * 16 + p * 8;
            float d[4][4][4];
#pragma unroll
            for (int g = 0; g < 4; g++) {
                float b0 = biasp[g * 64 + js + 2 * (l & 3)];
                float b1 = biasp[g * 64 + js + 2 * (l & 3) + 1];
#pragma unroll
                for (int mt = 0; mt < 4; mt++) {
                    d[mt][g][0] = b0; d[mt][g][1] = b1;
                    d[mt][g][2] = b0; d[mt][g][3] = b1;
                }
            }
#pragma unroll
            for (int kt = 0; kt < 8; kt++) {
                int k0 = kt * 16;
                int ah_base = (kt < 4) ? K2_H1H : K2_H2H;
                int al_base = (kt < 4) ? K2_H1L : K2_H2L;
                int ka = (kt < 4) ? k0 : (k0 - 64);
                uint32_t bh[4][2], bl[4][2];
#pragma unroll
                for (int g = 0; g < 4; g++) {
                    ldsm_x2(bh[g], sb + K2_W2H + (uint32_t)(g * 64 + js + rowBn) * 272 + k0 * 2 + colB);
                    ldsm_x2(bl[g], sb + K2_W2L + (uint32_t)(g * 64 + js + rowBn) * 272 + k0 * 2 + colB);
                }
#pragma unroll
                for (int mt = 0; mt < 4; mt++) {
                    uint32_t ah[4], al[4];
                    ldsm_x4(ah, sb + ah_base + (uint32_t)(m0 + 16 * mt + rowA) * 144 + ka * 2 + colA);
                    ldsm_x4(al, sb + al_base + (uint32_t)(m0 + 16 * mt + rowA) * 144 + ka * 2 + colA);
#pragma unroll
                    for (int g = 0; g < 4; g++) {
                        mma16816(d[mt][g], ah, bh[g]);
                        mma16816(d[mt][g], al, bh[g]);
                        mma16816(d[mt][g], ah, bl[g]);
                    }
                }
            }
#pragma unroll
            for (int mt = 0; mt < 4; mt++)
#pragma unroll
            for (int rr = 0; rr < 2; rr++) {
                float hv2[2];
#pragma unroll
                for (int jj = 0; jj < 2; jj++) {
                    int reg = rr * 2 + jj;
                    float gi = d[mt][0][reg], gf = d[mt][1][reg];
                    float gg = d[mt][2][reg], go = d[mt][3][reg];
                    int ci = ((p * 4 + mt) * 2 + rr) * 2 + jj;
                    float cc = sigf(gf) * c[ci] + sigf(gi) * tanha(gg);
                    c[ci] = cc;
                    float hh = sigf(go) * tanha(cc);
                    hreg[ci] = hh;
                    hv2[jj] = hh;
                }
                if (t == T_STEPS - 1) {
                    int r = m0 + 16 * mt + (l >> 2) + 8 * rr;
                    int j0 = nw * 16 + p * 8 + 2 * (l & 3);
                    atomicAdd(scr + r, hv2[0] * wfcp[j0] + hv2[1] * wfcp[j0 + 1]);
                }
            }
        }
        __syncthreads();
    }

    if (tid < 128) out[gb + tid] = scr[tid] + bfc[0];
}

extern "C" void kernel_launch(void* const* d_in, const int* in_sizes, int n_in,
                              void* d_out, int out_size)
{
    const float* x    = (const float*)d_in[0];
    const float* Wih0 = (const float*)d_in[1];
    const float* Whh0 = (const float*)d_in[2];
    const float* bih0 = (const float*)d_in[3];
    const float* bhh0 = (const float*)d_in[4];
    const float* Wih1 = (const float*)d_in[5];
    const float* Whh1 = (const float*)d_in[6];
    const float* bih1 = (const float*)d_in[7];
    const float* bhh1 = (const float*)d_in[8];
    const float* Wfc  = (const float*)d_in[9];
    const float* bfc  = (const float*)d_in[10];
    float* out = (float*)d_out;

    cudaFuncSetAttribute(lstm_l1, cudaFuncAttributeMaxDynamicSharedMemorySize, K1_SMEM);
    cudaFuncSetAttribute(lstm_l2, cudaFuncAttributeMaxDynamicSharedMemorySize, K2_SMEM);

    lstm_l1<<<NBLK, THREADS, K1_SMEM>>>(x, Wih0, Whh0, bih0, bhh0);
    lstm_l2<<<NBLK, THREADS, K2_SMEM>>>(Wih1, Whh1, bih1, bhh1, Wfc, bfc, out);
}

// round 8
// speedup vs baseline: 2.1323x; 1.1241x over previous
#include <cuda_runtime.h>
#include <cuda_bf16.h>
#include <cstdint>
#include <cstring>

#define T_STEPS 8
#define NBLK 1024
#define THREADS 512

// layer-1 h sequence, packed (bf16 hi | bf16 lo) u32: [blk][t][m(128)][j(64)]
__device__ uint32_t g_h1[(size_t)NBLK * T_STEPS * 8192];

// ---------------- kernel1 smem layout (bytes) ----------------
#define K1_BX    0         // [256][40] bf16 (80B rows): x-weights folded
#define K1_W1H   20480     // Whh0 hi [256][72] (144B rows)
#define K1_W1L   57344
#define K1_XT    94208     // x A-tile [128][40]
#define K1_H1H   104448    // h1 hi [128][72]
#define K1_H1L   122880
#define K1_BIAS  141312    // fp32 [256]
#define K1_SMEM  142336

// ---------------- kernel2 smem layout ----------------
#define K2_W2H   0         // [Wih1|Whh1] hi [256][136] (272B rows)
#define K2_W2L   69632
#define K2_H1H   139264    // h1 hi [128][72]
#define K2_H1L   157696
#define K2_H2H   176128
#define K2_H2L   194560
#define K2_BIAS  212992
#define K2_WFC   214016    // fp32 [64]
#define K2_SCR   214272    // fp32 [128] FC scratch
#define K2_SMEM  214784

__device__ __forceinline__ uint32_t smem_u32(const void* p) {
    uint32_t a;
    asm("{ .reg .u64 t; cvta.to.shared.u64 t, %1; cvt.u32.u64 %0, t; }" : "=r"(a) : "l"(p));
    return a;
}
__device__ __forceinline__ void mma16816(float* d, const uint32_t* a, const uint32_t* b) {
    asm volatile("mma.sync.aligned.m16n8k16.row.col.f32.bf16.bf16.f32 "
        "{%0,%1,%2,%3},{%4,%5,%6,%7},{%8,%9},{%0,%1,%2,%3};"
        : "+f"(d[0]), "+f"(d[1]), "+f"(d[2]), "+f"(d[3])
        : "r"(a[0]), "r"(a[1]), "r"(a[2]), "r"(a[3]), "r"(b[0]), "r"(b[1]));
}
__device__ __forceinline__ void ldsm_x4(uint32_t* r, uint32_t addr) {
    asm volatile("ldmatrix.sync.aligned.m8n8.x4.shared.b16 {%0,%1,%2,%3}, [%4];"
        : "=r"(r[0]), "=r"(r[1]), "=r"(r[2]), "=r"(r[3]) : "r"(addr));
}
__device__ __forceinline__ void ldsm_x2(uint32_t* r, uint32_t addr) {
    asm volatile("ldmatrix.sync.aligned.m8n8.x2.shared.b16 {%0,%1}, [%2];"
        : "=r"(r[0]), "=r"(r[1]) : "r"(addr));
}
__device__ __forceinline__ float tanha(float x) {
    float r; asm("tanh.approx.f32 %0, %1;" : "=f"(r) : "f"(x)); return r;
}
__device__ __forceinline__ float sigf(float x) { return fmaf(tanha(0.5f * x), 0.5f, 0.5f); }

__device__ __forceinline__ void split_bf16(float v, __nv_bfloat16& hi, __nv_bfloat16& lo) {
    hi = __float2bfloat16(v);
    lo = __float2bfloat16(v - __bfloat162float(hi));
}

// ============================ kernel 1: layer 1 ============================
__global__ void __launch_bounds__(THREADS, 1) lstm_l1(
    const float* __restrict__ x,
    const float* __restrict__ Wih0, const float* __restrict__ Whh0,
    const float* __restrict__ bih0, const float* __restrict__ bhh0)
{
    extern __shared__ char sm[];
    const int tid = threadIdx.x;

    for (int i = tid; i < K1_SMEM / 4; i += THREADS) ((uint32_t*)sm)[i] = 0;
    __syncthreads();

    for (int idx = tid; idx < 1536; idx += THREADS) {
        int r = idx / 6, i = idx - r * 6;
        __nv_bfloat16 hi, lo; split_bf16(Wih0[idx], hi, lo);
        *(__nv_bfloat16*)(sm + K1_BX + r * 80 + i * 2) = hi;       // vs xhi
        *(__nv_bfloat16*)(sm + K1_BX + r * 80 + (8 + i) * 2) = hi; // vs xlo
        *(__nv_bfloat16*)(sm + K1_BX + r * 80 + (16 + i) * 2) = lo;// vs xhi
    }
    for (int idx = tid; idx < 16384; idx += THREADS) {
        int r = idx >> 6, k = idx & 63;
        __nv_bfloat16 hi, lo; split_bf16(Whh0[idx], hi, lo);
        *(__nv_bfloat16*)(sm + K1_W1H + r * 144 + k * 2) = hi;
        *(__nv_bfloat16*)(sm + K1_W1L + r * 144 + k * 2) = lo;
    }
    if (tid < 256) ((float*)(sm + K1_BIAS))[tid] = bih0[tid] + bhh0[tid];
    __syncthreads();

    const int l = tid & 31, w = tid >> 5, mw = w >> 2, nw = w & 3;
    const int m0 = mw * 32;
    const uint32_t sb = smem_u32(sm);
    const int rowA = l & 15;
    const int colA = (l & 16) ? 16 : 0;
    const int rowBn = l & 7;
    const int colB = (l & 8) ? 16 : 0;
    const size_t gb = (size_t)blockIdx.x * 128;
    const float* biasp = (const float*)(sm + K1_BIAS);

    float c[16], hreg[16];
#pragma unroll
    for (int i = 0; i < 16; i++) { c[i] = 0.0f; hreg[i] = 0.0f; }

    // prefetch x(0)
    float pfx[6];
    const float* xrow_g = x + (gb + tid) * 48;
    if (tid < 128) {
#pragma unroll
        for (int i = 0; i < 6; i++) pfx[i] = xrow_g[i];
    }

    for (int t = 0; t < T_STEPS; t++) {
        // ---- phase A: write h(t-1) tiles, stage x(t) from prefetch ----
        if (t > 0) {
#pragma unroll
            for (int p = 0; p < 2; p++)
#pragma unroll
            for (int mt = 0; mt < 2; mt++)
#pragma unroll
            for (int rr = 0; rr < 2; rr++)
#pragma unroll
            for (int jj = 0; jj < 2; jj++) {
                int r = m0 + 16 * mt + (l >> 2) + 8 * rr;
                int j = nw * 16 + p * 8 + 2 * (l & 3) + jj;
                __nv_bfloat16 hi, lo;
                split_bf16(hreg[((p * 2 + mt) * 2 + rr) * 2 + jj], hi, lo);
                *(__nv_bfloat16*)(sm + K1_H1H + r * 144 + j * 2) = hi;
                *(__nv_bfloat16*)(sm + K1_H1L + r * 144 + j * 2) = lo;
            }
        }
        if (tid < 128) {
            char* xrow = sm + K1_XT + tid * 80;
#pragma unroll
            for (int i = 0; i < 6; i++) {
                __nv_bfloat16 hi, lo; split_bf16(pfx[i], hi, lo);
                *(__nv_bfloat16*)(xrow + i * 2) = hi;
                *(__nv_bfloat16*)(xrow + (8 + i) * 2) = lo;
                *(__nv_bfloat16*)(xrow + (16 + i) * 2) = hi;
            }
        }
        __syncthreads();

        // ---- phase B: prefetch x(t+1); pack h(t-1) to gmem; MMA; epilogue ----
        if (tid < 128 && t < T_STEPS - 1) {
#pragma unroll
            for (int i = 0; i < 6; i++) pfx[i] = xrow_g[(t + 1) * 6 + i];
        }
        if (t > 0) {
            uint32_t* gdst = g_h1 + ((size_t)blockIdx.x * T_STEPS + (t - 1)) * 8192;
#pragma unroll
            for (int q = 0; q < 4; q++) {
                int idx = q * 2048 + tid * 4;
                int m = idx >> 6, j = idx & 63;
                uint2 hv = *(uint2*)(sm + K1_H1H + m * 144 + j * 2);
                uint2 lv = *(uint2*)(sm + K1_H1L + m * 144 + j * 2);
                uint4 o;
                o.x = __byte_perm(hv.x, lv.x, 0x5410);
                o.y = __byte_perm(hv.x, lv.x, 0x7632);
                o.z = __byte_perm(hv.y, lv.y, 0x5410);
                o.w = __byte_perm(hv.y, lv.y, 0x7632);
                *(uint4*)(gdst + idx) = o;
            }
        }

#pragma unroll
        for (int p = 0; p < 2; p++) {
            const int js = nw * 16 + p * 8;
            float d[2][4][4];
#pragma unroll
            for (int g = 0; g < 4; g++) {
                float b0 = biasp[g * 64 + js + 2 * (l & 3)];
                float b1 = biasp[g * 64 + js + 2 * (l & 3) + 1];
#pragma unroll
                for (int mt = 0; mt < 2; mt++) {
                    d[mt][g][0] = b0; d[mt][g][1] = b1;
                    d[mt][g][2] = b0; d[mt][g][3] = b1;
                }
            }
            // x-part (K=32 folded tile)
#pragma unroll
            for (int kt = 0; kt < 2; kt++) {
                int k0 = kt * 16;
                uint32_t bx[4][2];
#pragma unroll
                for (int g = 0; g < 4; g++)
                    ldsm_x2(bx[g], sb + K1_BX + (uint32_t)(g * 64 + js + rowBn) * 80 + k0 * 2 + colB);
#pragma unroll
                for (int mt = 0; mt < 2; mt++) {
                    uint32_t a[4];
                    ldsm_x4(a, sb + K1_XT + (uint32_t)(m0 + 16 * mt + rowA) * 80 + k0 * 2 + colA);
#pragma unroll
                    for (int g = 0; g < 4; g++) mma16816(d[mt][g], a, bx[g]);
                }
            }
            // h-part: 3-term split over K=64
#pragma unroll
            for (int kt = 0; kt < 4; kt++) {
                int k0 = kt * 16;
                uint32_t bh[4][2], bl[4][2];
#pragma unroll
                for (int g = 0; g < 4; g++) {
                    ldsm_x2(bh[g], sb + K1_W1H + (uint32_t)(g * 64 + js + rowBn) * 144 + k0 * 2 + colB);
                    ldsm_x2(bl[g], sb + K1_W1L + (uint32_t)(g * 64 + js + rowBn) * 144 + k0 * 2 + colB);
                }
#pragma unroll
                for (int mt = 0; mt < 2; mt++) {
                    uint32_t ah[4], al[4];
                    ldsm_x4(ah, sb + K1_H1H + (uint32_t)(m0 + 16 * mt + rowA) * 144 + k0 * 2 + colA);
                    ldsm_x4(al, sb + K1_H1L + (uint32_t)(m0 + 16 * mt + rowA) * 144 + k0 * 2 + colA);
#pragma unroll
                    for (int g = 0; g < 4; g++) {
                        mma16816(d[mt][g], ah, bh[g]);
                        mma16816(d[mt][g], al, bh[g]);
                        mma16816(d[mt][g], ah, bl[g]);
                    }
                }
            }
            // epilogue -> registers
#pragma unroll
            for (int mt = 0; mt < 2; mt++)
#pragma unroll
            for (int rr = 0; rr < 2; rr++)
#pragma unroll
            for (int jj = 0; jj < 2; jj++) {
                int reg = rr * 2 + jj;
                float gi = d[mt][0][reg], gf = d[mt][1][reg];
                float gg = d[mt][2][reg], go = d[mt][3][reg];
                int ci = ((p * 2 + mt) * 2 + rr) * 2 + jj;
                float cc = sigf(gf) * c[ci] + sigf(gi) * tanha(gg);
                c[ci] = cc;
                hreg[ci] = sigf(go) * tanha(cc);
            }
        }
        __syncthreads();
    }

    // final h(7): write tiles then pack
#pragma unroll
    for (int p = 0; p < 2; p++)
#pragma unroll
    for (int mt = 0; mt < 2; mt++)
#pragma unroll
    for (int rr = 0; rr < 2; rr++)
#pragma unroll
    for (int jj = 0; jj < 2; jj++) {
        int r = m0 + 16 * mt + (l >> 2) + 8 * rr;
        int j = nw * 16 + p * 8 + 2 * (l & 3) + jj;
        __nv_bfloat16 hi, lo;
        split_bf16(hreg[((p * 2 + mt) * 2 + rr) * 2 + jj], hi, lo);
        *(__nv_bfloat16*)(sm + K1_H1H + r * 144 + j * 2) = hi;
        *(__nv_bfloat16*)(sm + K1_H1L + r * 144 + j * 2) = lo;
    }
    __syncthreads();
    {
        uint32_t* gdst = g_h1 + ((size_t)blockIdx.x * T_STEPS + 7) * 8192;
#pragma unroll
        for (int q = 0; q < 4; q++) {
            int idx = q * 2048 + tid * 4;
            int m = idx >> 6, j = idx & 63;
            uint2 hv = *(uint2*)(sm + K1_H1H + m * 144 + j * 2);
            uint2 lv = *(uint2*)(sm + K1_H1L + m * 144 + j * 2);
            uint4 o;
            o.x = __byte_perm(hv.x, lv.x, 0x5410);
            o.y = __byte_perm(hv.x, lv.x, 0x7632);
            o.z = __byte_perm(hv.y, lv.y, 0x5410);
            o.w = __byte_perm(hv.y, lv.y, 0x7632);
            *(uint4*)(gdst + idx) = o;
        }
    }
}

// ============================ kernel 2: layer 2 + FC ============================
__global__ void __launch_bounds__(THREADS, 1) lstm_l2(
    const float* __restrict__ Wih1, const float* __restrict__ Whh1,
    const float* __restrict__ bih1, const float* __restrict__ bhh1,
    const float* __restrict__ Wfc, const float* __restrict__ bfc,
    float* __restrict__ out)
{
    extern __shared__ char sm[];
    const int tid = threadIdx.x;

    for (int i = tid; i < K2_SMEM / 4; i += THREADS) ((uint32_t*)sm)[i] = 0;
    __syncthreads();

    for (int idx = tid; idx < 16384; idx += THREADS) {
        int r = idx >> 6, k = idx & 63;
        __nv_bfloat16 hi, lo;
        split_bf16(Wih1[idx], hi, lo);
        *(__nv_bfloat16*)(sm + K2_W2H + r * 272 + k * 2) = hi;
        *(__nv_bfloat16*)(sm + K2_W2L + r * 272 + k * 2) = lo;
        split_bf16(Whh1[idx], hi, lo);
        *(__nv_bfloat16*)(sm + K2_W2H + r * 272 + (64 + k) * 2) = hi;
        *(__nv_bfloat16*)(sm + K2_W2L + r * 272 + (64 + k) * 2) = lo;
    }
    if (tid < 256) ((float*)(sm + K2_BIAS))[tid] = bih1[tid] + bhh1[tid];
    if (tid < 64)  ((float*)(sm + K2_WFC))[tid] = Wfc[tid];
    __syncthreads();

    const int l = tid & 31, w = tid >> 5, mw = w >> 2, nw = w & 3;
    const int m0 = mw * 32;
    const uint32_t sb = smem_u32(sm);
    const int rowA = l & 15;
    const int colA = (l & 16) ? 16 : 0;
    const int rowBn = l & 7;
    const int colB = (l & 8) ? 16 : 0;
    const size_t gb = (size_t)blockIdx.x * 128;
    const float* biasp = (const float*)(sm + K2_BIAS);
    const float* wfcp  = (const float*)(sm + K2_WFC);
    float* scr = (float*)(sm + K2_SCR);

    float c[16], hreg[16];
#pragma unroll
    for (int i = 0; i < 16; i++) { c[i] = 0.0f; hreg[i] = 0.0f; }

    const uint32_t* gsrc_base = g_h1 + (size_t)blockIdx.x * T_STEPS * 8192;

    // prefetch h1(0)
    uint4 pf[4];
#pragma unroll
    for (int q = 0; q < 4; q++)
        pf[q] = *(const uint4*)(gsrc_base + q * 2048 + tid * 4);

    for (int t = 0; t < T_STEPS; t++) {
        // ---- phase A: write h2(t-1) tiles, unpack prefetched h1(t) ----
        if (t > 0) {
#pragma unroll
            for (int p = 0; p < 2; p++)
#pragma unroll
            for (int mt = 0; mt < 2; mt++)
#pragma unroll
            for (int rr = 0; rr < 2; rr++)
#pragma unroll
            for (int jj = 0; jj < 2; jj++) {
                int r = m0 + 16 * mt + (l >> 2) + 8 * rr;
                int j = nw * 16 + p * 8 + 2 * (l & 3) + jj;
                __nv_bfloat16 hi, lo;
                split_bf16(hreg[((p * 2 + mt) * 2 + rr) * 2 + jj], hi, lo);
                *(__nv_bfloat16*)(sm + K2_H2H + r * 144 + j * 2) = hi;
                *(__nv_bfloat16*)(sm + K2_H2L + r * 144 + j * 2) = lo;
            }
        }
#pragma unroll
        for (int q = 0; q < 4; q++) {
            int idx = q * 2048 + tid * 4;
            int m = idx >> 6, j = idx & 63;
            uint4 v = pf[q];
            uint2 hv, lv;
            hv.x = __byte_perm(v.x, v.y, 0x5410);
            lv.x = __byte_perm(v.x, v.y, 0x7632);
            hv.y = __byte_perm(v.z, v.w, 0x5410);
            lv.y = __byte_perm(v.z, v.w, 0x7632);
            *(uint2*)(sm + K2_H1H + m * 144 + j * 2) = hv;
            *(uint2*)(sm + K2_H1L + m * 144 + j * 2) = lv;
        }
        __syncthreads();

        // ---- phase B: prefetch h1(t+1); MMA + epilogue ----
        if (t < T_STEPS - 1) {
            const uint32_t* gsrc = gsrc_base + (size_t)(t + 1) * 8192;
#pragma unroll
            for (int q = 0; q < 4; q++)
                pf[q] = *(const uint4*)(gsrc + q * 2048 + tid * 4);
        }

#pragma unroll
        for (int p = 0; p < 2; p++) {
            const int js = nw * 16 + p * 8;
            float d[2][4][4];
#pragma unroll
            for (int g = 0; g < 4; g++) {
                float b0 = biasp[g * 64 + js + 2 * (l & 3)];
                float b1 = biasp[g * 64 + js + 2 * (l & 3) + 1];
#pragma unroll
                for (int mt = 0; mt < 2; mt++) {
                    d[mt][g][0] = b0; d[mt][g][1] = b1;
                    d[mt][g][2] = b0; d[mt][g][3] = b1;
                }
            }
#pragma unroll
            for (int kt = 0; kt < 8; kt++) {
                int k0 = kt * 16;
                int ah_base = (kt < 4) ? K2_H1H : K2_H2H;
                int al_base = (kt < 4) ? K2_H1L : K2_H2L;
                int ka = (kt < 4) ? k0 : (k0 - 64);
                uint32_t bh[4][2], bl[4][2];
#pragma unroll
                for (int g = 0; g < 4; g++) {
                    ldsm_x2(bh[g], sb + K2_W2H + (uint32_t)(g * 64 + js + rowBn) * 272 + k0 * 2 + colB);
                    ldsm_x2(bl[g], sb + K2_W2L + (uint32_t)(g * 64 + js + rowBn) * 272 + k0 * 2 + colB);
                }
#pragma unroll
                for (int mt = 0; mt < 2; mt++) {
                    uint32_t ah[4], al[4];
                    ldsm_x4(ah, sb + ah_base + (uint32_t)(m0 + 16 * mt + rowA) * 144 + ka * 2 + colA);
                    ldsm_x4(al, sb + al_base + (uint32_t)(m0 + 16 * mt + rowA) * 144 + ka * 2 + colA);
#pragma unroll
                    for (int g = 0; g < 4; g++) {
                        mma16816(d[mt][g], ah, bh[g]);
                        mma16816(d[mt][g], al, bh[g]);
                        mma16816(d[mt][g], ah, bl[g]);
                    }
                }
            }
#pragma unroll
            for (int mt = 0; mt < 2; mt++)
#pragma unroll
            for (int rr = 0; rr < 2; rr++) {
                float hv2[2];
#pragma unroll
                for (int jj = 0; jj < 2; jj++) {
                    int reg = rr * 2 + jj;
                    float gi = d[mt][0][reg], gf = d[mt][1][reg];
                    float gg = d[mt][2][reg], go = d[mt][3][reg];
                    int ci = ((p * 2 + mt) * 2 + rr) * 2 + jj;
                    float cc = sigf(gf) * c[ci] + sigf(gi) * tanha(gg);
                    c[ci] = cc;
                    float hh = sigf(go) * tanha(cc);
                    hreg[ci] = hh;
                    hv2[jj] = hh;
                }
                if (t == T_STEPS - 1) {
                    int r = m0 + 16 * mt + (l >> 2) + 8 * rr;
                    int j0 = nw * 16 + p * 8 + 2 * (l & 3);
                    atomicAdd(scr + r, hv2[0] * wfcp[j0] + hv2[1] * wfcp[j0 + 1]);
                }
            }
        }
        __syncthreads();
    }

    if (tid < 128) out[gb + tid] = scr[tid] + bfc[0];
}

extern "C" void kernel_launch(void* const* d_in, const int* in_sizes, int n_in,
                              void* d_out, int out_size)
{
    const float* x    = (const float*)d_in[0];
    const float* Wih0 = (const float*)d_in[1];
    const float* Whh0 = (const float*)d_in[2];
    const float* bih0 = (const float*)d_in[3];
    const float* bhh0 = (const float*)d_in[4];
    const float* Wih1 = (const float*)d_in[5];
    const float* Whh1 = (const float*)d_in[6];
    const float* bih1 = (const float*)d_in[7];
    const float* bhh1 = (const float*)d_in[8];
    const float* Wfc  = (const float*)d_in[9];
    const float* bfc  = (const float*)d_in[10];
    float* out = (float*)d_out;

    cudaFuncSetAttribute(lstm_l1, cudaFuncAttributeMaxDynamicSharedMemorySize, K1_SMEM);
    cudaFuncSetAttribute(lstm_l2, cudaFuncAttributeMaxDynamicSharedMemorySize, K2_SMEM);

    lstm_l1<<<NBLK, THREADS, K1_SMEM>>>(x, Wih0, Whh0, bih0, bhh0);
    lstm_l2<<<NBLK, THREADS, K2_SMEM>>>(Wih1, Whh1, bih1, bhh1, Wfc, bfc, out);
}

// round 9
// speedup vs baseline: 3.1431x; 1.4740x over previous
#include <cuda_runtime.h>
#include <cuda_fp16.h>
#include <cstdint>
#include <cstring>

#define T_STEPS 8
#define NBLK 1024
#define THREADS 512

// layer-1 h sequence, plain fp16: [blk][t][4096 u32] (word w: m=w>>5, j=(w&31)*2)
__device__ uint32_t g_h1[(size_t)NBLK * T_STEPS * 4096];

// ---------------- kernel1 smem layout (bytes) ----------------
#define K1_BX    0         // [256][40] fp16 (80B rows): cols0-5 Wxhi, cols8-13 Wxlo
#define K1_W1H   20480     // Whh0 hi [256][72] (144B rows)
#define K1_W1L   57344     // Whh0 lo
#define K1_XT    94208     // x A-tile [128][40]: cols0-5 x, cols8-13 x
#define K1_H1H   104448    // h1 fp16 [128][72]
#define K1_BIAS  141312    // fp32 [256]
#define K1_SMEM  142336

// ---------------- kernel2 smem layout ----------------
#define K2_W2H   0         // [Wih1|Whh1] hi [256][136] (272B rows)
#define K2_W2L   69632     // lo
#define K2_H1H   139264    // h1 fp16 [128][72]
#define K2_H2H   157696    // h2 fp16 [128][72]
#define K2_BIAS  176128
#define K2_WFC   177152    // fp32 [64]
#define K2_SCR   177408    // fp32 [128] FC scratch
#define K2_SMEM  177920

__device__ __forceinline__ uint32_t smem_u32(const void* p) {
    uint32_t a;
    asm("{ .reg .u64 t; cvta.to.shared.u64 t, %1; cvt.u32.u64 %0, t; }" : "=r"(a) : "l"(p));
    return a;
}
__device__ __forceinline__ void mma16816(float* d, const uint32_t* a, const uint32_t* b) {
    asm volatile("mma.sync.aligned.m16n8k16.row.col.f32.f16.f16.f32 "
        "{%0,%1,%2,%3},{%4,%5,%6,%7},{%8,%9},{%0,%1,%2,%3};"
        : "+f"(d[0]), "+f"(d[1]), "+f"(d[2]), "+f"(d[3])
        : "r"(a[0]), "r"(a[1]), "r"(a[2]), "r"(a[3]), "r"(b[0]), "r"(b[1]));
}
__device__ __forceinline__ void ldsm_x4(uint32_t* r, uint32_t addr) {
    asm volatile("ldmatrix.sync.aligned.m8n8.x4.shared.b16 {%0,%1,%2,%3}, [%4];"
        : "=r"(r[0]), "=r"(r[1]), "=r"(r[2]), "=r"(r[3]) : "r"(addr));
}
__device__ __forceinline__ void ldsm_x2(uint32_t* r, uint32_t addr) {
    asm volatile("ldmatrix.sync.aligned.m8n8.x2.shared.b16 {%0,%1}, [%2];"
        : "=r"(r[0]), "=r"(r[1]) : "r"(addr));
}
__device__ __forceinline__ float tanha(float x) {
    float r; asm("tanh.approx.f32 %0, %1;" : "=f"(r) : "f"(x)); return r;
}
__device__ __forceinline__ float sigf(float x) { return fmaf(tanha(0.5f * x), 0.5f, 0.5f); }

__device__ __forceinline__ void split_f16(float v, __half& hi, __half& lo) {
    hi = __float2half(v);
    lo = __float2half(v - __half2float(hi));
}

// ============================ kernel 1: layer 1 ============================
__global__ void __launch_bounds__(THREADS, 1) lstm_l1(
    const float* __restrict__ x,
    const float* __restrict__ Wih0, const float* __restrict__ Whh0,
    const float* __restrict__ bih0, const float* __restrict__ bhh0)
{
    extern __shared__ char sm[];
    const int tid = threadIdx.x;

    for (int i = tid; i < K1_SMEM / 4; i += THREADS) ((uint32_t*)sm)[i] = 0;
    __syncthreads();

    for (int idx = tid; idx < 1536; idx += THREADS) {
        int r = idx / 6, i = idx - r * 6;
        __half hi, lo; split_f16(Wih0[idx], hi, lo);
        *(__half*)(sm + K1_BX + r * 80 + i * 2) = hi;        // vs x (band 0)
        *(__half*)(sm + K1_BX + r * 80 + (8 + i) * 2) = lo;  // vs x (band 1)
    }
    for (int idx = tid; idx < 16384; idx += THREADS) {
        int r = idx >> 6, k = idx & 63;
        __half hi, lo; split_f16(Whh0[idx], hi, lo);
        *(__half*)(sm + K1_W1H + r * 144 + k * 2) = hi;
        *(__half*)(sm + K1_W1L + r * 144 + k * 2) = lo;
    }
    if (tid < 256) ((float*)(sm + K1_BIAS))[tid] = bih0[tid] + bhh0[tid];
    __syncthreads();

    const int l = tid & 31, w = tid >> 5, mw = w >> 2, nw = w & 3;
    const int m0 = mw * 32;
    const uint32_t sb = smem_u32(sm);
    const int rowA = l & 15;
    const int colA = (l & 16) ? 16 : 0;
    const int rowBn = l & 7;
    const int colB = (l & 8) ? 16 : 0;
    const size_t gb = (size_t)blockIdx.x * 128;
    const float* biasp = (const float*)(sm + K1_BIAS);

    float c[16], hreg[16];
#pragma unroll
    for (int i = 0; i < 16; i++) { c[i] = 0.0f; hreg[i] = 0.0f; }

    // prefetch x(0)
    float pfx[6];
    const float* xrow_g = x + (gb + tid) * 48;
    if (tid < 128) {
#pragma unroll
        for (int i = 0; i < 6; i++) pfx[i] = xrow_g[i];
    }

    for (int t = 0; t < T_STEPS; t++) {
        // ---- phase A: write h(t-1) tile, stage x(t) from prefetch ----
        if (t > 0) {
#pragma unroll
            for (int p = 0; p < 2; p++)
#pragma unroll
            for (int mt = 0; mt < 2; mt++)
#pragma unroll
            for (int rr = 0; rr < 2; rr++)
#pragma unroll
            for (int jj = 0; jj < 2; jj++) {
                int r = m0 + 16 * mt + (l >> 2) + 8 * rr;
                int j = nw * 16 + p * 8 + 2 * (l & 3) + jj;
                *(__half*)(sm + K1_H1H + r * 144 + j * 2) =
                    __float2half(hreg[((p * 2 + mt) * 2 + rr) * 2 + jj]);
            }
        }
        if (tid < 128) {
            char* xrow = sm + K1_XT + tid * 80;
#pragma unroll
            for (int i = 0; i < 6; i++) {
                __half xv = __float2half(pfx[i]);
                *(__half*)(xrow + i * 2) = xv;
                *(__half*)(xrow + (8 + i) * 2) = xv;
            }
        }
        __syncthreads();

        // ---- phase B: prefetch x(t+1); pack h(t-1) to gmem; MMA; epilogue ----
        if (tid < 128 && t < T_STEPS - 1) {
#pragma unroll
            for (int i = 0; i < 6; i++) pfx[i] = xrow_g[(t + 1) * 6 + i];
        }
        if (t > 0) {
            uint32_t* gdst = g_h1 + ((size_t)blockIdx.x * T_STEPS + (t - 1)) * 4096;
#pragma unroll
            for (int q = 0; q < 2; q++) {
                int iu = q * 2048 + tid * 4;          // u32 index
                int m = iu >> 5, jh = (iu & 31) * 2;  // j of first half
                *(uint4*)(gdst + iu) = *(uint4*)(sm + K1_H1H + m * 144 + jh * 2);
            }
        }

#pragma unroll
        for (int p = 0; p < 2; p++) {
            const int js = nw * 16 + p * 8;
            float d[2][4][4];
#pragma unroll
            for (int g = 0; g < 4; g++) {
                float b0 = biasp[g * 64 + js + 2 * (l & 3)];
                float b1 = biasp[g * 64 + js + 2 * (l & 3) + 1];
#pragma unroll
                for (int mt = 0; mt < 2; mt++) {
                    d[mt][g][0] = b0; d[mt][g][1] = b1;
                    d[mt][g][2] = b0; d[mt][g][3] = b1;
                }
            }
            // x-part: single K=16 chunk (Whi band 0, Wlo band 1, x duplicated)
            {
                uint32_t bx[4][2];
#pragma unroll
                for (int g = 0; g < 4; g++)
                    ldsm_x2(bx[g], sb + K1_BX + (uint32_t)(g * 64 + js + rowBn) * 80 + colB);
#pragma unroll
                for (int mt = 0; mt < 2; mt++) {
                    uint32_t a[4];
                    ldsm_x4(a, sb + K1_XT + (uint32_t)(m0 + 16 * mt + rowA) * 80 + colA);
#pragma unroll
                    for (int g = 0; g < 4; g++) mma16816(d[mt][g], a, bx[g]);
                }
            }
            // h-part: 2-term weight split over K=64
#pragma unroll
            for (int kt = 0; kt < 4; kt++) {
                int k0 = kt * 16;
                uint32_t bh[4][2], bl[4][2];
#pragma unroll
                for (int g = 0; g < 4; g++) {
                    ldsm_x2(bh[g], sb + K1_W1H + (uint32_t)(g * 64 + js + rowBn) * 144 + k0 * 2 + colB);
                    ldsm_x2(bl[g], sb + K1_W1L + (uint32_t)(g * 64 + js + rowBn) * 144 + k0 * 2 + colB);
                }
#pragma unroll
                for (int mt = 0; mt < 2; mt++) {
                    uint32_t ah[4];
                    ldsm_x4(ah, sb + K1_H1H + (uint32_t)(m0 + 16 * mt + rowA) * 144 + k0 * 2 + colA);
#pragma unroll
                    for (int g = 0; g < 4; g++) {
                        mma16816(d[mt][g], ah, bh[g]);
                        mma16816(d[mt][g], ah, bl[g]);
                    }
                }
            }
            // epilogue -> registers
#pragma unroll
            for (int mt = 0; mt < 2; mt++)
#pragma unroll
            for (int rr = 0; rr < 2; rr++)
#pragma unroll
            for (int jj = 0; jj < 2; jj++) {
                int reg = rr * 2 + jj;
                float gi = d[mt][0][reg], gf = d[mt][1][reg];
                float gg = d[mt][2][reg], go = d[mt][3][reg];
                int ci = ((p * 2 + mt) * 2 + rr) * 2 + jj;
                float cc = sigf(gf) * c[ci] + sigf(gi) * tanha(gg);
                c[ci] = cc;
                hreg[ci] = sigf(go) * tanha(cc);
            }
        }
        __syncthreads();
    }

    // final h(7): write tile then pack
#pragma unroll
    for (int p = 0; p < 2; p++)
#pragma unroll
    for (int mt = 0; mt < 2; mt++)
#pragma unroll
    for (int rr = 0; rr < 2; rr++)
#pragma unroll
    for (int jj = 0; jj < 2; jj++) {
        int r = m0 + 16 * mt + (l >> 2) + 8 * rr;
        int j = nw * 16 + p * 8 + 2 * (l & 3) + jj;
        *(__half*)(sm + K1_H1H + r * 144 + j * 2) =
            __float2half(hreg[((p * 2 + mt) * 2 + rr) * 2 + jj]);
    }
    __syncthreads();
    {
        uint32_t* gdst = g_h1 + ((size_t)blockIdx.x * T_STEPS + 7) * 4096;
#pragma unroll
        for (int q = 0; q < 2; q++) {
            int iu = q * 2048 + tid * 4;
            int m = iu >> 5, jh = (iu & 31) * 2;
            *(uint4*)(gdst + iu) = *(uint4*)(sm + K1_H1H + m * 144 + jh * 2);
        }
    }
}

// ============================ kernel 2: layer 2 + FC ============================
__global__ void __launch_bounds__(THREADS, 1) lstm_l2(
    const float* __restrict__ Wih1, const float* __restrict__ Whh1,
    const float* __restrict__ bih1, const float* __restrict__ bhh1,
    const float* __restrict__ Wfc, const float* __restrict__ bfc,
    float* __restrict__ out)
{
    extern __shared__ char sm[];
    const int tid = threadIdx.x;

    for (int i = tid; i < K2_SMEM / 4; i += THREADS) ((uint32_t*)sm)[i] = 0;
    __syncthreads();

    for (int idx = tid; idx < 16384; idx += THREADS) {
        int r = idx >> 6, k = idx & 63;
        __half hi, lo;
        split_f16(Wih1[idx], hi, lo);
        *(__half*)(sm + K2_W2H + r * 272 + k * 2) = hi;
        *(__half*)(sm + K2_W2L + r * 272 + k * 2) = lo;
        split_f16(Whh1[idx], hi, lo);
        *(__half*)(sm + K2_W2H + r * 272 + (64 + k) * 2) = hi;
        *(__half*)(sm + K2_W2L + r * 272 + (64 + k) * 2) = lo;
    }
    if (tid < 256) ((float*)(sm + K2_BIAS))[tid] = bih1[tid] + bhh1[tid];
    if (tid < 64)  ((float*)(sm + K2_WFC))[tid] = Wfc[tid];
    __syncthreads();

    const int l = tid & 31, w = tid >> 5, mw = w >> 2, nw = w & 3;
    const int m0 = mw * 32;
    const uint32_t sb = smem_u32(sm);
    const int rowA = l & 15;
    const int colA = (l & 16) ? 16 : 0;
    const int rowBn = l & 7;
    const int colB = (l & 8) ? 16 : 0;
    const size_t gb = (size_t)blockIdx.x * 128;
    const float* biasp = (const float*)(sm + K2_BIAS);
    const float* wfcp  = (const float*)(sm + K2_WFC);
    float* scr = (float*)(sm + K2_SCR);

    float c[16], hreg[16];
#pragma unroll
    for (int i = 0; i < 16; i++) { c[i] = 0.0f; hreg[i] = 0.0f; }

    const uint32_t* gsrc_base = g_h1 + (size_t)blockIdx.x * T_STEPS * 4096;

    // prefetch h1(0)
    uint4 pf[2];
#pragma unroll
    for (int q = 0; q < 2; q++)
        pf[q] = *(const uint4*)(gsrc_base + q * 2048 + tid * 4);

    for (int t = 0; t < T_STEPS; t++) {
        // ---- phase A: write h2(t-1) tile, unpack prefetched h1(t) ----
        if (t > 0) {
#pragma unroll
            for (int p = 0; p < 2; p++)
#pragma unroll
            for (int mt = 0; mt < 2; mt++)
#pragma unroll
            for (int rr = 0; rr < 2; rr++)
#pragma unroll
            for (int jj = 0; jj < 2; jj++) {
                int r = m0 + 16 * mt + (l >> 2) + 8 * rr;
                int j = nw * 16 + p * 8 + 2 * (l & 3) + jj;
                *(__half*)(sm + K2_H2H + r * 144 + j * 2) =
                    __float2half(hreg[((p * 2 + mt) * 2 + rr) * 2 + jj]);
            }
        }
#pragma unroll
        for (int q = 0; q < 2; q++) {
            int iu = q * 2048 + tid * 4;
            int m = iu >> 5, jh = (iu & 31) * 2;
            *(uint4*)(sm + K2_H1H + m * 144 + jh * 2) = pf[q];
        }
        __syncthreads();

        // ---- phase B: prefetch h1(t+1); MMA + epilogue ----
        if (t < T_STEPS - 1) {
            const uint32_t* gsrc = gsrc_base + (size_t)(t + 1) * 4096;
#pragma unroll
            for (int q = 0; q < 2; q++)
                pf[q] = *(const uint4*)(gsrc + q * 2048 + tid * 4);
        }

#pragma unroll
        for (int p = 0; p < 2; p++) {
            const int js = nw * 16 + p * 8;
            float d[2][4][4];
#pragma unroll
            for (int g = 0; g < 4; g++) {
                float b0 = biasp[g * 64 + js + 2 * (l & 3)];
                float b1 = biasp[g * 64 + js + 2 * (l & 3) + 1];
#pragma unroll
                for (int mt = 0; mt < 2; mt++) {
                    d[mt][g][0] = b0; d[mt][g][1] = b1;
                    d[mt][g][2] = b0; d[mt][g][3] = b1;
                }
            }
#pragma unroll
            for (int kt = 0; kt < 8; kt++) {
                int k0 = kt * 16;
                int ah_base = (kt < 4) ? K2_H1H : K2_H2H;
                int ka = (kt < 4) ? k0 : (k0 - 64);
                uint32_t bh[4][2], bl[4][2];
#pragma unroll
                for (int g = 0; g < 4; g++) {
                    ldsm_x2(bh[g], sb + K2_W2H + (uint32_t)(g * 64 + js + rowBn) * 272 + k0 * 2 + colB);
                    ldsm_x2(bl[g], sb + K2_W2L + (uint32_t)(g * 64 + js + rowBn) * 272 + k0 * 2 + colB);
                }
#pragma unroll
                for (int mt = 0; mt < 2; mt++) {
                    uint32_t ah[4];
                    ldsm_x4(ah, sb + ah_base + (uint32_t)(m0 + 16 * mt + rowA) * 144 + ka * 2 + colA);
#pragma unroll
                    for (int g = 0; g < 4; g++) {
                        mma16816(d[mt][g], ah, bh[g]);
                        mma16816(d[mt][g], ah, bl[g]);
                    }
                }
            }
#pragma unroll
            for (int mt = 0; mt < 2; mt++)
#pragma unroll
            for (int rr = 0; rr < 2; rr++) {
                float hv2[2];
#pragma unroll
                for (int jj = 0; jj < 2; jj++) {
                    int reg = rr * 2 + jj;
                    float gi = d[mt][0][reg], gf = d[mt][1][reg];
                    float gg = d[mt][2][reg], go = d[mt][3][reg];
                    int ci = ((p * 2 + mt) * 2 + rr) * 2 + jj;
                    float cc = sigf(gf) * c[ci] + sigf(gi) * tanha(gg);
                    c[ci] = cc;
                    float hh = sigf(go) * tanha(cc);
                    hreg[ci] = hh;
                    hv2[jj] = hh;
                }
                if (t == T_STEPS - 1) {
                    int r = m0 + 16 * mt + (l >> 2) + 8 * rr;
                    int j0 = nw * 16 + p * 8 + 2 * (l & 3);
                    atomicAdd(scr + r, hv2[0] * wfcp[j0] + hv2[1] * wfcp[j0 + 1]);
                }
            }
        }
        __syncthreads();
    }

    if (tid < 128) out[gb + tid] = scr[tid] + bfc[0];
}

extern "C" void kernel_launch(void* const* d_in, const int* in_sizes, int n_in,
                              void* d_out, int out_size)
{
    const float* x    = (const float*)d_in[0];
    const float* Wih0 = (const float*)d_in[1];
    const float* Whh0 = (const float*)d_in[2];
    const float* bih0 = (const float*)d_in[3];
    const float* bhh0 = (const float*)d_in[4];
    const float* Wih1 = (const float*)d_in[5];
    const float* Whh1 = (const float*)d_in[6];
    const float* bih1 = (const float*)d_in[7];
    const float* bhh1 = (const float*)d_in[8];
    const float* Wfc  = (const float*)d_in[9];
    const float* bfc  = (const float*)d_in[10];
    float* out = (float*)d_out;

    cudaFuncSetAttribute(lstm_l1, cudaFuncAttributeMaxDynamicSharedMemorySize, K1_SMEM);
    cudaFuncSetAttribute(lstm_l2, cudaFuncAttributeMaxDynamicSharedMemorySize, K2_SMEM);

    lstm_l1<<<NBLK, THREADS, K1_SMEM>>>(x, Wih0, Whh0, bih0, bhh0);
    lstm_l2<<<NBLK, THREADS, K2_SMEM>>>(Wih1, Whh1, bih1, bhh1, Wfc, bfc, out);
}

// round 10
// speedup vs baseline: 4.6783x; 1.4885x over previous
#include <cuda_runtime.h>
#include <cuda_fp16.h>
#include <cstdint>
#include <cstring>

#define T_STEPS 8
#define NBLK 2048
#define THREADS 256

// layer-1 h sequence, fp16: [blk][t][2048 u32] (word w: m=w>>5, j=(w&31)*2)
__device__ uint32_t g_h1[(size_t)NBLK * T_STEPS * 2048];

// ---------------- kernel1 smem layout (bytes) ----------------
#define K1_BX    0         // [256][40] fp16 (80B rows): cols0-5 Wx
#define K1_W1H   20480     // Whh0 [256][72] (144B rows)
#define K1_XT    57344     // x A-tile [64][40]
#define K1_H1H   62464     // h1 fp16 [64][72]
#define K1_BIAS  71680     // fp32 [256]
#define K1_SMEM  72704

// ---------------- kernel2 smem layout ----------------
#define K2_W2H   0         // [Wih1|Whh1] [256][136] (272B rows)
#define K2_H1H   69632     // h1 fp16 [64][72]
#define K2_H2H   78848     // h2 fp16 [64][72]
#define K2_BIAS  88064     // fp32 [256]
#define K2_WFC   89088     // fp32 [64]
#define K2_SCR   89344     // fp32 [64]
#define K2_SMEM  89600

__device__ __forceinline__ uint32_t smem_u32(const void* p) {
    uint32_t a;
    asm("{ .reg .u64 t; cvta.to.shared.u64 t, %1; cvt.u32.u64 %0, t; }" : "=r"(a) : "l"(p));
    return a;
}
__device__ __forceinline__ void mma16816(float* d, const uint32_t* a, const uint32_t* b) {
    asm volatile("mma.sync.aligned.m16n8k16.row.col.f32.f16.f16.f32 "
        "{%0,%1,%2,%3},{%4,%5,%6,%7},{%8,%9},{%0,%1,%2,%3};"
        : "+f"(d[0]), "+f"(d[1]), "+f"(d[2]), "+f"(d[3])
        : "r"(a[0]), "r"(a[1]), "r"(a[2]), "r"(a[3]), "r"(b[0]), "r"(b[1]));
}
__device__ __forceinline__ void ldsm_x4(uint32_t* r, uint32_t addr) {
    asm volatile("ldmatrix.sync.aligned.m8n8.x4.shared.b16 {%0,%1,%2,%3}, [%4];"
        : "=r"(r[0]), "=r"(r[1]), "=r"(r[2]), "=r"(r[3]) : "r"(addr));
}
__device__ __forceinline__ void ldsm_x2(uint32_t* r, uint32_t addr) {
    asm volatile("ldmatrix.sync.aligned.m8n8.x2.shared.b16 {%0,%1}, [%2];"
        : "=r"(r[0]), "=r"(r[1]) : "r"(addr));
}
__device__ __forceinline__ float tanha(float x) {
    float r; asm("tanh.approx.f32 %0, %1;" : "=f"(r) : "f"(x)); return r;
}
__device__ __forceinline__ float sigf(float x) { return fmaf(tanha(0.5f * x), 0.5f, 0.5f); }

// ============================ kernel 1: layer 1 ============================
__global__ void __launch_bounds__(THREADS, 2) lstm_l1(
    const float* __restrict__ x,
    const float* __restrict__ Wih0, const float* __restrict__ Whh0,
    const float* __restrict__ bih0, const float* __restrict__ bhh0)
{
    extern __shared__ char sm[];
    const int tid = threadIdx.x;

    for (int i = tid; i < K1_SMEM / 4; i += THREADS) ((uint32_t*)sm)[i] = 0;
    __syncthreads();

    for (int idx = tid; idx < 1536; idx += THREADS) {
        int r = idx / 6, i = idx - r * 6;
        *(__half*)(sm + K1_BX + r * 80 + i * 2) = __float2half(Wih0[idx]);
    }
    for (int idx = tid; idx < 16384; idx += THREADS) {
        int r = idx >> 6, k = idx & 63;
        *(__half*)(sm + K1_W1H + r * 144 + k * 2) = __float2half(Whh0[idx]);
    }
    if (tid < 256) ((float*)(sm + K1_BIAS))[tid] = bih0[tid] + bhh0[tid];
    __syncthreads();

    const int l = tid & 31, w = tid >> 5, mw = w >> 2, nw = w & 3;
    const int m0 = mw * 32;
    const uint32_t sb = smem_u32(sm);
    const int rowA = l & 15;
    const int colA = (l & 16) ? 16 : 0;
    const int rowBn = l & 7;
    const int colB = (l & 8) ? 16 : 0;
    const size_t gb = (size_t)blockIdx.x * 64;
    const float* biasp = (const float*)(sm + K1_BIAS);

    float c[16], hreg[16];
#pragma unroll
    for (int i = 0; i < 16; i++) { c[i] = 0.0f; hreg[i] = 0.0f; }

    // prefetch x(0)
    float pfx[6];
    const float* xrow_g = x + (gb + tid) * 48;
    if (tid < 64) {
#pragma unroll
        for (int i = 0; i < 6; i++) pfx[i] = xrow_g[i];
    }

    for (int t = 0; t < T_STEPS; t++) {
        // ---- phase A: write h(t-1) tile, stage x(t) from prefetch ----
        if (t > 0) {
#pragma unroll
            for (int p = 0; p < 2; p++)
#pragma unroll
            for (int mt = 0; mt < 2; mt++)
#pragma unroll
            for (int rr = 0; rr < 2; rr++)
#pragma unroll
            for (int jj = 0; jj < 2; jj++) {
                int r = m0 + 16 * mt + (l >> 2) + 8 * rr;
                int j = nw * 16 + p * 8 + 2 * (l & 3) + jj;
                *(__half*)(sm + K1_H1H + r * 144 + j * 2) =
                    __float2half(hreg[((p * 2 + mt) * 2 + rr) * 2 + jj]);
            }
        }
        if (tid < 64) {
            char* xrow = sm + K1_XT + tid * 80;
#pragma unroll
            for (int i = 0; i < 6; i++)
                *(__half*)(xrow + i * 2) = __float2half(pfx[i]);
        }
        __syncthreads();

        // ---- phase B: prefetch x(t+1); pack h(t-1) to gmem; MMA; epilogue ----
        if (tid < 64 && t < T_STEPS - 1) {
#pragma unroll
            for (int i = 0; i < 6; i++) pfx[i] = xrow_g[(t + 1) * 6 + i];
        }
        if (t > 0) {
            uint32_t* gdst = g_h1 + ((size_t)blockIdx.x * T_STEPS + (t - 1)) * 2048;
#pragma unroll
            for (int q = 0; q < 2; q++) {
                int iu = q * 1024 + tid * 4;
                int m = iu >> 5, jh = (iu & 31) * 2;
                *(uint4*)(gdst + iu) = *(uint4*)(sm + K1_H1H + m * 144 + jh * 2);
            }
        }

#pragma unroll
        for (int p = 0; p < 2; p++) {
            const int js = nw * 16 + p * 8;
            float d[2][4][4];
#pragma unroll
            for (int g = 0; g < 4; g++) {
                float b0 = biasp[g * 64 + js + 2 * (l & 3)];
                float b1 = biasp[g * 64 + js + 2 * (l & 3) + 1];
#pragma unroll
                for (int mt = 0; mt < 2; mt++) {
                    d[mt][g][0] = b0; d[mt][g][1] = b1;
                    d[mt][g][2] = b0; d[mt][g][3] = b1;
                }
            }
            // x-part: single K=16 chunk (cols 0-5 live, rest zero)
            {
                uint32_t bx[4][2];
#pragma unroll
                for (int g = 0; g < 4; g++)
                    ldsm_x2(bx[g], sb + K1_BX + (uint32_t)(g * 64 + js + rowBn) * 80 + colB);
#pragma unroll
                for (int mt = 0; mt < 2; mt++) {
                    uint32_t a[4];
                    ldsm_x4(a, sb + K1_XT + (uint32_t)(m0 + 16 * mt + rowA) * 80 + colA);
#pragma unroll
                    for (int g = 0; g < 4; g++) mma16816(d[mt][g], a, bx[g]);
                }
            }
            // h-part: single-term over K=64
#pragma unroll
            for (int kt = 0; kt < 4; kt++) {
                int k0 = kt * 16;
                uint32_t bh[4][2];
#pragma unroll
                for (int g = 0; g < 4; g++)
                    ldsm_x2(bh[g], sb + K1_W1H + (uint32_t)(g * 64 + js + rowBn) * 144 + k0 * 2 + colB);
#pragma unroll
                for (int mt = 0; mt < 2; mt++) {
                    uint32_t ah[4];
                    ldsm_x4(ah, sb + K1_H1H + (uint32_t)(m0 + 16 * mt + rowA) * 144 + k0 * 2 + colA);
#pragma unroll
                    for (int g = 0; g < 4; g++) mma16816(d[mt][g], ah, bh[g]);
                }
            }
            // epilogue -> registers
#pragma unroll
            for (int mt = 0; mt < 2; mt++)
#pragma unroll
            for (int rr = 0; rr < 2; rr++)
#pragma unroll
            for (int jj = 0; jj < 2; jj++) {
                int reg = rr * 2 + jj;
                float gi = d[mt][0][reg], gf = d[mt][1][reg];
                float gg = d[mt][2][reg], go = d[mt][3][reg];
                int ci = ((p * 2 + mt) * 2 + rr) * 2 + jj;
                float cc = sigf(gf) * c[ci] + sigf(gi) * tanha(gg);
                c[ci] = cc;
                hreg[ci] = sigf(go) * tanha(cc);
            }
        }
        __syncthreads();
    }

    // final h(7): write tile then pack
#pragma unroll
    for (int p = 0; p < 2; p++)
#pragma unroll
    for (int mt = 0; mt < 2; mt++)
#pragma unroll
    for (int rr = 0; rr < 2; rr++)
#pragma unroll
    for (int jj = 0; jj < 2; jj++) {
        int r = m0 + 16 * mt + (l >> 2) + 8 * rr;
        int j = nw * 16 + p * 8 + 2 * (l & 3) + jj;
        *(__half*)(sm + K1_H1H + r * 144 + j * 2) =
            __float2half(hreg[((p * 2 + mt) * 2 + rr) * 2 + jj]);
    }
    __syncthreads();
    {
        uint32_t* gdst = g_h1 + ((size_t)blockIdx.x * T_STEPS + 7) * 2048;
#pragma unroll
        for (int q = 0; q < 2; q++) {
            int iu = q * 1024 + tid * 4;
            int m = iu >> 5, jh = (iu & 31) * 2;
            *(uint4*)(gdst + iu) = *(uint4*)(sm + K1_H1H + m * 144 + jh * 2);
        }
    }
}

// ============================ kernel 2: layer 2 + FC ============================
__global__ void __launch_bounds__(THREADS, 2) lstm_l2(
    const float* __restrict__ Wih1, const float* __restrict__ Whh1,
    const float* __restrict__ bih1, const float* __restrict__ bhh1,
    const float* __restrict__ Wfc, const float* __restrict__ bfc,
    float* __restrict__ out)
{
    extern __shared__ char sm[];
    const int tid = threadIdx.x;

    for (int i = tid; i < K2_SMEM / 4; i += THREADS) ((uint32_t*)sm)[i] = 0;
    __syncthreads();

    for (int idx = tid; idx < 16384; idx += THREADS) {
        int r = idx >> 6, k = idx & 63;
        *(__half*)(sm + K2_W2H + r * 272 + k * 2) = __float2half(Wih1[idx]);
        *(__half*)(sm + K2_W2H + r * 272 + (64 + k) * 2) = __float2half(Whh1[idx]);
    }
    if (tid < 256) ((float*)(sm + K2_BIAS))[tid] = bih1[tid] + bhh1[tid];
    if (tid < 64)  ((float*)(sm + K2_WFC))[tid] = Wfc[tid];
    __syncthreads();

    const int l = tid & 31, w = tid >> 5, mw = w >> 2, nw = w & 3;
    const int m0 = mw * 32;
    const uint32_t sb = smem_u32(sm);
    const int rowA = l & 15;
    const int colA = (l & 16) ? 16 : 0;
    const int rowBn = l & 7;
    const int colB = (l & 8) ? 16 : 0;
    const size_t gb = (size_t)blockIdx.x * 64;
    const float* biasp = (const float*)(sm + K2_BIAS);
    const float* wfcp  = (const float*)(sm + K2_WFC);
    float* scr = (float*)(sm + K2_SCR);

    float c[16], hreg[16];
#pragma unroll
    for (int i = 0; i < 16; i++) { c[i] = 0.0f; hreg[i] = 0.0f; }

    const uint32_t* gsrc_base = g_h1 + (size_t)blockIdx.x * T_STEPS * 2048;

    // prefetch h1(0)
    uint4 pf[2];
#pragma unroll
    for (int q = 0; q < 2; q++)
        pf[q] = *(const uint4*)(gsrc_base + q * 1024 + tid * 4);

    for (int t = 0; t < T_STEPS; t++) {
        // ---- phase A: write h2(t-1) tile, unpack prefetched h1(t) ----
        if (t > 0) {
#pragma unroll
            for (int p = 0; p < 2; p++)
#pragma unroll
            for (int mt = 0; mt < 2; mt++)
#pragma unroll
            for (int rr = 0; rr < 2; rr++)
#pragma unroll
            for (int jj = 0; jj < 2; jj++) {
                int r = m0 + 16 * mt + (l >> 2) + 8 * rr;
                int j = nw * 16 + p * 8 + 2 * (l & 3) + jj;
                *(__half*)(sm + K2_H2H + r * 144 + j * 2) =
                    __float2half(hreg[((p * 2 + mt) * 2 + rr) * 2 + jj]);
            }
        }
#pragma unroll
        for (int q = 0; q < 2; q++) {
            int iu = q * 1024 + tid * 4;
            int m = iu >> 5, jh = (iu & 31) * 2;
            *(uint4*)(sm + K2_H1H + m * 144 + jh * 2) = pf[q];
        }
        __syncthreads();

        // ---- phase B: prefetch h1(t+1); MMA + epilogue ----
        if (t < T_STEPS - 1) {
            const uint32_t* gsrc = gsrc_base + (size_t)(t + 1) * 2048;
#pragma unroll
            for (int q = 0; q < 2; q++)
                pf[q] = *(const uint4*)(gsrc + q * 1024 + tid * 4);
        }

#pragma unroll
        for (int p = 0; p < 2; p++) {
            const int js = nw * 16 + p * 8;
            float d[2][4][4];
#pragma unroll
            for (int g = 0; g < 4; g++) {
                float b0 = biasp[g * 64 + js + 2 * (l & 3)];
                float b1 = biasp[g * 64 + js + 2 * (l & 3) + 1];
#pragma unroll
                for (int mt = 0; mt < 2; mt++) {
                    d[mt][g][0] = b0; d[mt][g][1] = b1;
                    d[mt][g][2] = b0; d[mt][g][3] = b1;
                }
            }
#pragma unroll
            for (int kt = 0; kt < 8; kt++) {
                int k0 = kt * 16;
                int ah_base = (kt < 4) ? K2_H1H : K2_H2H;
                int ka = (kt < 4) ? k0 : (k0 - 64);
                uint32_t bh[4][2];
#pragma unroll
                for (int g = 0; g < 4; g++)
                    ldsm_x2(bh[g], sb + K2_W2H + (uint32_t)(g * 64 + js + rowBn) * 272 + k0 * 2 + colB);
#pragma unroll
                for (int mt = 0; mt < 2; mt++) {
                    uint32_t ah[4];
                    ldsm_x4(ah, sb + ah_base + (uint32_t)(m0 + 16 * mt + rowA) * 144 + ka * 2 + colA);
#pragma unroll
                    for (int g = 0; g < 4; g++) mma16816(d[mt][g], ah, bh[g]);
                }
            }
#pragma unroll
            for (int mt = 0; mt < 2; mt++)
#pragma unroll
            for (int rr = 0; rr < 2; rr++) {
                float hv2[2];
#pragma unroll
                for (int jj = 0; jj < 2; jj++) {
                    int reg = rr * 2 + jj;
                    float gi = d[mt][0][reg], gf = d[mt][1][reg];
                    float gg = d[mt][2][reg], go = d[mt][3][reg];
                    int ci = ((p * 2 + mt) * 2 + rr) * 2 + jj;
                    float cc = sigf(gf) * c[ci] + sigf(gi) * tanha(gg);
                    c[ci] = cc;
                    float hh = sigf(go) * tanha(cc);
                    hreg[ci] = hh;
                    hv2[jj] = hh;
                }
                if (t == T_STEPS - 1) {
                    int r = m0 + 16 * mt + (l >> 2) + 8 * rr;
                    int j0 = nw * 16 + p * 8 + 2 * (l & 3);
                    atomicAdd(scr + r, hv2[0] * wfcp[j0] + hv2[1] * wfcp[j0 + 1]);
                }
            }
        }
        __syncthreads();
    }

    if (tid < 64) out[gb + tid] = scr[tid] + bfc[0];
}

extern "C" void kernel_launch(void* const* d_in, const int* in_sizes, int n_in,
                              void* d_out, int out_size)
{
    const float* x    = (const float*)d_in[0];
    const float* Wih0 = (const float*)d_in[1];
    const float* Whh0 = (const float*)d_in[2];
    const float* bih0 = (const float*)d_in[3];
    const float* bhh0 = (const float*)d_in[4];
    const float* Wih1 = (const float*)d_in[5];
    const float* Whh1 = (const float*)d_in[6];
    const float* bih1 = (const float*)d_in[7];
    const float* bhh1 = (const float*)d_in[8];
    const float* Wfc  = (const float*)d_in[9];
    const float* bfc  = (const float*)d_in[10];
    float* out = (float*)d_out;

    cudaFuncSetAttribute(lstm_l1, cudaFuncAttributeMaxDynamicSharedMemorySize, K1_SMEM);
    cudaFuncSetAttribute(lstm_l2, cudaFuncAttributeMaxDynamicSharedMemorySize, K2_SMEM);

    lstm_l1<<<NBLK, THREADS, K1_SMEM>>>(x, Wih0, Whh0, bih0, bhh0);
    lstm_l2<<<NBLK, THREADS, K2_SMEM>>>(Wih1, Whh1, bih1, bhh1, Wfc, bfc, out);
}

// round 11
// speedup vs baseline: 4.7332x; 1.0117x over previous
#include <cuda_runtime.h>
#include <cuda_fp16.h>
#include <cstdint>
#include <cstring>

#define T_STEPS 8
#define NBLK 2048
#define THREADS 256

// layer-1 h sequence, fp16: [blk][t][2048 u32] (word w: m=w>>5, j=(w&31)*2)
__device__ uint32_t g_h1[(size_t)NBLK * T_STEPS * 2048];

// ---------------- kernel1 smem layout (bytes) ----------------
#define K1_BX    0         // [256][40] fp16 (80B rows): cols0-5 Wx, rest 0
#define K1_W1    20480     // Whh0 [256][72] (144B rows)
#define K1_X0    57344     // x tile buf0 [64][40]
#define K1_X1    62464     // x tile buf1
#define K1_H0    67584     // h1 buf0 [64][72]
#define K1_H1    76800     // h1 buf1
#define K1_BIAS  86016     // fp32 [256]
#define K1_SMEM  87040

// ---------------- kernel2 smem layout ----------------
#define K2_W2    0         // [Wih1|Whh1] [256][136] (272B rows)
#define K2_H1A   69632     // h1 buf0 [64][72]
#define K2_H1B   78848
#define K2_H2A   88064     // h2 buf0
#define K2_H2B   97280
#define K2_BIAS  106496    // fp32 [256]
#define K2_WFC   107520    // fp32 [64]
#define K2_SCR   107776    // fp32 [64]
#define K2_SMEM  108032

__device__ __forceinline__ uint32_t smem_u32(const void* p) {
    uint32_t a;
    asm("{ .reg .u64 t; cvta.to.shared.u64 t, %1; cvt.u32.u64 %0, t; }" : "=r"(a) : "l"(p));
    return a;
}
__device__ __forceinline__ void mma16816(float* d, const uint32_t* a, const uint32_t* b) {
    asm volatile("mma.sync.aligned.m16n8k16.row.col.f32.f16.f16.f32 "
        "{%0,%1,%2,%3},{%4,%5,%6,%7},{%8,%9},{%0,%1,%2,%3};"
        : "+f"(d[0]), "+f"(d[1]), "+f"(d[2]), "+f"(d[3])
        : "r"(a[0]), "r"(a[1]), "r"(a[2]), "r"(a[3]), "r"(b[0]), "r"(b[1]));
}
__device__ __forceinline__ void ldsm_x4(uint32_t* r, uint32_t addr) {
    asm volatile("ldmatrix.sync.aligned.m8n8.x4.shared.b16 {%0,%1,%2,%3}, [%4];"
        : "=r"(r[0]), "=r"(r[1]), "=r"(r[2]), "=r"(r[3]) : "r"(addr));
}
__device__ __forceinline__ float tanha(float x) {
    float r; asm("tanh.approx.f32 %0, %1;" : "=f"(r) : "f"(x)); return r;
}
__device__ __forceinline__ float sigf(float x) { return fmaf(tanha(0.5f * x), 0.5f, 0.5f); }

// ============================ kernel 1: layer 1 ============================
__global__ void __launch_bounds__(THREADS, 2) lstm_l1(
    const float* __restrict__ x,
    const float* __restrict__ Wih0, const float* __restrict__ Whh0,
    const float* __restrict__ bih0, const float* __restrict__ bhh0)
{
    extern __shared__ char sm[];
    const int tid = threadIdx.x;

    for (int i = tid; i < K1_SMEM / 4; i += THREADS) ((uint32_t*)sm)[i] = 0;
    __syncthreads();

    for (int idx = tid; idx < 1536; idx += THREADS) {
        int r = idx / 6, i = idx - r * 6;
        *(__half*)(sm + K1_BX + r * 80 + i * 2) = __float2half(Wih0[idx]);
    }
    for (int idx = tid; idx < 16384; idx += THREADS) {
        int r = idx >> 6, k = idx & 63;
        *(__half*)(sm + K1_W1 + r * 144 + k * 2) = __float2half(Whh0[idx]);
    }
    if (tid < 256) ((float*)(sm + K1_BIAS))[tid] = bih0[tid] + bhh0[tid];

    const int l = tid & 31, w = tid >> 5, mw = w >> 2, nw = w & 3;
    const int m0 = mw * 32;
    const uint32_t sb = smem_u32(sm);
    const int rowA = l & 15;
    const int colA = (l & 16) ? 16 : 0;
    const int rowB2 = (l & 7) + ((l >> 4) & 1) * 64;  // gate-pair x4 B load
    const int colB2 = ((l >> 3) & 1) * 16;
    const size_t gb = (size_t)blockIdx.x * 64;
    const float* biasp = (const float*)(sm + K1_BIAS);

    float c[16];
#pragma unroll
    for (int i = 0; i < 16; i++) c[i] = 0.0f;

    // prefetch + stage x(0) into X0
    float pfx[6];
    const float* xrow_g = x + (gb + tid) * 48;
    if (tid < 64) {
#pragma unroll
        for (int i = 0; i < 6; i++) pfx[i] = xrow_g[i];
        char* xrow = sm + K1_X0 + tid * 80;
#pragma unroll
        for (int i = 0; i < 6; i++)
            *(__half*)(xrow + i * 2) = __float2half(pfx[i]);
    }
    __syncthreads();

    const uint32_t XB[2] = { sb + K1_X0, sb + K1_X1 };
    const uint32_t HB[2] = { sb + K1_H0, sb + K1_H1 };
    const char*    HBc[2] = { sm + K1_H0, sm + K1_H1 };
    char*          HBw[2] = { sm + K1_H0, sm + K1_H1 };

    for (int t = 0; t < T_STEPS; t++) {
        const int cur = t & 1, nxt = cur ^ 1;

        // prefetch x(t+1)
        if (tid < 64 && t < T_STEPS - 1) {
#pragma unroll
            for (int i = 0; i < 6; i++) pfx[i] = xrow_g[(t + 1) * 6 + i];
        }
        // pack h(t-1) -> gmem (reads HB[cur])
        if (t > 0) {
            uint32_t* gdst = g_h1 + ((size_t)blockIdx.x * T_STEPS + (t - 1)) * 2048;
#pragma unroll
            for (int q = 0; q < 2; q++) {
                int iu = q * 1024 + tid * 4;
                int m = iu >> 5, jh = (iu & 31) * 2;
                *(uint4*)(gdst + iu) = *(const uint4*)(HBc[cur] + m * 144 + jh * 2);
            }
        }

        // ---- MMA phase: both p halves accumulated together ----
        float d[2][2][4][4];
#pragma unroll
        for (int p = 0; p < 2; p++) {
            const int js = nw * 16 + p * 8;
#pragma unroll
            for (int g = 0; g < 4; g++) {
                float2 bv = *(const float2*)(biasp + g * 64 + js + 2 * (l & 3));
#pragma unroll
                for (int mt = 0; mt < 2; mt++) {
                    d[p][mt][g][0] = bv.x; d[p][mt][g][1] = bv.y;
                    d[p][mt][g][2] = bv.x; d[p][mt][g][3] = bv.y;
                }
            }
        }
        // x-part: one K=16 chunk
        {
            uint32_t ah0[4], ah1[4];
            ldsm_x4(ah0, XB[cur] + (uint32_t)(m0 + rowA) * 80 + colA);
            ldsm_x4(ah1, XB[cur] + (uint32_t)(m0 + 16 + rowA) * 80 + colA);
#pragma unroll
            for (int p = 0; p < 2; p++) {
                const int js = nw * 16 + p * 8;
                uint32_t b01[4], b23[4];
                ldsm_x4(b01, sb + K1_BX + (uint32_t)(js + rowB2) * 80 + colB2);
                ldsm_x4(b23, sb + K1_BX + (uint32_t)(128 + js + rowB2) * 80 + colB2);
                mma16816(d[p][0][0], ah0, b01);     mma16816(d[p][0][1], ah0, b01 + 2);
                mma16816(d[p][0][2], ah0, b23);     mma16816(d[p][0][3], ah0, b23 + 2);
                mma16816(d[p][1][0], ah1, b01);     mma16816(d[p][1][1], ah1, b01 + 2);
                mma16816(d[p][1][2], ah1, b23);     mma16816(d[p][1][3], ah1, b23 + 2);
            }
        }
        // h-part: K=64
#pragma unroll
        for (int kt = 0; kt < 4; kt++) {
            const int k0 = kt * 16;
            uint32_t ah0[4], ah1[4];
            ldsm_x4(ah0, HB[cur] + (uint32_t)(m0 + rowA) * 144 + k0 * 2 + colA);
            ldsm_x4(ah1, HB[cur] + (uint32_t)(m0 + 16 + rowA) * 144 + k0 * 2 + colA);
#pragma unroll
            for (int p = 0; p < 2; p++) {
                const int js = nw * 16 + p * 8;
                uint32_t b01[4], b23[4];
                ldsm_x4(b01, sb + K1_W1 + (uint32_t)(js + rowB2) * 144 + k0 * 2 + colB2);
                ldsm_x4(b23, sb + K1_W1 + (uint32_t)(128 + js + rowB2) * 144 + k0 * 2 + colB2);
                mma16816(d[p][0][0], ah0, b01);     mma16816(d[p][0][1], ah0, b01 + 2);
                mma16816(d[p][0][2], ah0, b23);     mma16816(d[p][0][3], ah0, b23 + 2);
                mma16816(d[p][1][0], ah1, b01);     mma16816(d[p][1][1], ah1, b01 + 2);
                mma16816(d[p][1][2], ah1, b23);     mma16816(d[p][1][3], ah1, b23 + 2);
            }
        }

        // stage x(t+1) into the other buffer
        if (tid < 64 && t < T_STEPS - 1) {
            char* xrow = (nxt ? sm + K1_X1 : sm + K1_X0) + tid * 80;
#pragma unroll
            for (int i = 0; i < 6; i++)
                *(__half*)(xrow + i * 2) = __float2half(pfx[i]);
        }

        // ---- epilogue: write h(t) directly into HB[nxt] ----
#pragma unroll
        for (int p = 0; p < 2; p++) {
            const int js = nw * 16 + p * 8;
#pragma unroll
            for (int mt = 0; mt < 2; mt++)
#pragma unroll
            for (int rr = 0; rr < 2; rr++) {
                float hv[2];
#pragma unroll
                for (int jj = 0; jj < 2; jj++) {
                    int reg = rr * 2 + jj;
                    float gi = d[p][0 + mt][0][reg];
                    gi = d[p][mt][0][reg];
                    float gf = d[p][mt][1][reg];
                    float gg = d[p][mt][2][reg];
                    float go = d[p][mt][3][reg];
                    int ci = ((p * 2 + mt) * 2 + rr) * 2 + jj;
                    float cc = sigf(gf) * c[ci] + sigf(gi) * tanha(gg);
                    c[ci] = cc;
                    hv[jj] = sigf(go) * tanha(cc);
                }
                int r = m0 + 16 * mt + (l >> 2) + 8 * rr;
                int j0 = js + 2 * (l & 3);
                *(__half2*)(HBw[nxt] + r * 144 + j0 * 2) =
                    __halves2half2(__float2half(hv[0]), __float2half(hv[1]));
            }
        }
        __syncthreads();
    }

    // pack h(7) (sits in HB[0] after t=7 wrote nxt=0)
    {
        uint32_t* gdst = g_h1 + ((size_t)blockIdx.x * T_STEPS + 7) * 2048;
#pragma unroll
        for (int q = 0; q < 2; q++) {
            int iu = q * 1024 + tid * 4;
            int m = iu >> 5, jh = (iu & 31) * 2;
            *(uint4*)(gdst + iu) = *(const uint4*)(HBc[0] + m * 144 + jh * 2);
        }
    }
}

// ============================ kernel 2: layer 2 + FC ============================
__global__ void __launch_bounds__(THREADS, 2) lstm_l2(
    const float* __restrict__ Wih1, const float* __restrict__ Whh1,
    const float* __restrict__ bih1, const float* __restrict__ bhh1,
    const float* __restrict__ Wfc, const float* __restrict__ bfc,
    float* __restrict__ out)
{
    extern __shared__ char sm[];
    const int tid = threadIdx.x;

    for (int i = tid; i < K2_SMEM / 4; i += THREADS) ((uint32_t*)sm)[i] = 0;
    __syncthreads();

    for (int idx = tid; idx < 16384; idx += THREADS) {
        int r = idx >> 6, k = idx & 63;
        *(__half*)(sm + K2_W2 + r * 272 + k * 2) = __float2half(Wih1[idx]);
        *(__half*)(sm + K2_W2 + r * 272 + (64 + k) * 2) = __float2half(Whh1[idx]);
    }
    if (tid < 256) ((float*)(sm + K2_BIAS))[tid] = bih1[tid] + bhh1[tid];
    if (tid < 64)  ((float*)(sm + K2_WFC))[tid] = Wfc[tid];

    const int l = tid & 31, w = tid >> 5, mw = w >> 2, nw = w & 3;
    const int m0 = mw * 32;
    const uint32_t sb = smem_u32(sm);
    const int rowA = l & 15;
    const int colA = (l & 16) ? 16 : 0;
    const int rowB2 = (l & 7) + ((l >> 4) & 1) * 64;
    const int colB2 = ((l >> 3) & 1) * 16;
    const size_t gb = (size_t)blockIdx.x * 64;
    const float* biasp = (const float*)(sm + K2_BIAS);
    const float* wfcp  = (const float*)(sm + K2_WFC);
    float* scr = (float*)(sm + K2_SCR);

    float c[16];
#pragma unroll
    for (int i = 0; i < 16; i++) c[i] = 0.0f;

    const uint32_t* gsrc_base = g_h1 + (size_t)blockIdx.x * T_STEPS * 2048;

    // prefetch + stage h1(0) into H1A
    uint4 pf[2];
#pragma unroll
    for (int q = 0; q < 2; q++)
        pf[q] = *(const uint4*)(gsrc_base + q * 1024 + tid * 4);
#pragma unroll
    for (int q = 0; q < 2; q++) {
        int iu = q * 1024 + tid * 4;
        int m = iu >> 5, jh = (iu & 31) * 2;
        *(uint4*)(sm + K2_H1A + m * 144 + jh * 2) = pf[q];
    }
    __syncthreads();

    const uint32_t H1B_[2] = { sb + K2_H1A, sb + K2_H1B };
    const uint32_t H2B_[2] = { sb + K2_H2A, sb + K2_H2B };
    char* H1w[2] = { sm + K2_H1A, sm + K2_H1B };
    char* H2w[2] = { sm + K2_H2A, sm + K2_H2B };

    for (int t = 0; t < T_STEPS; t++) {
        const int cur = t & 1, nxt = cur ^ 1;

        // prefetch h1(t+1)
        if (t < T_STEPS - 1) {
            const uint32_t* gsrc = gsrc_base + (size_t)(t + 1) * 2048;
#pragma unroll
            for (int q = 0; q < 2; q++)
                pf[q] = *(const uint4*)(gsrc + q * 1024 + tid * 4);
        }

        // ---- MMA phase ----
        float d[2][2][4][4];
#pragma unroll
        for (int p = 0; p < 2; p++) {
            const int js = nw * 16 + p * 8;
#pragma unroll
            for (int g = 0; g < 4; g++) {
                float2 bv = *(const float2*)(biasp + g * 64 + js + 2 * (l & 3));
#pragma unroll
                for (int mt = 0; mt < 2; mt++) {
                    d[p][mt][g][0] = bv.x; d[p][mt][g][1] = bv.y;
                    d[p][mt][g][2] = bv.x; d[p][mt][g][3] = bv.y;
                }
            }
        }
#pragma unroll
        for (int kt = 0; kt < 8; kt++) {
            const int k0 = kt * 16;
            const uint32_t abase = (kt < 4) ? H1B_[cur] : H2B_[cur];
            const int ka = (kt < 4) ? k0 : (k0 - 64);
            uint32_t ah0[4], ah1[4];
            ldsm_x4(ah0, abase + (uint32_t)(m0 + rowA) * 144 + ka * 2 + colA);
            ldsm_x4(ah1, abase + (uint32_t)(m0 + 16 + rowA) * 144 + ka * 2 + colA);
#pragma unroll
            for (int p = 0; p < 2; p++) {
                const int js = nw * 16 + p * 8;
                uint32_t b01[4], b23[4];
                ldsm_x4(b01, sb + K2_W2 + (uint32_t)(js + rowB2) * 272 + k0 * 2 + colB2);
                ldsm_x4(b23, sb + K2_W2 + (uint32_t)(128 + js + rowB2) * 272 + k0 * 2 + colB2);
                mma16816(d[p][0][0], ah0, b01);     mma16816(d[p][0][1], ah0, b01 + 2);
                mma16816(d[p][0][2], ah0, b23);     mma16816(d[p][0][3], ah0, b23 + 2);
                mma16816(d[p][1][0], ah1, b01);     mma16816(d[p][1][1], ah1, b01 + 2);
                mma16816(d[p][1][2], ah1, b23);     mma16816(d[p][1][3], ah1, b23 + 2);
            }
        }

        // unpack prefetched h1(t+1) into H1[nxt]
        if (t < T_STEPS - 1) {
#pragma unroll
            for (int q = 0; q < 2; q++) {
                int iu = q * 1024 + tid * 4;
                int m = iu >> 5, jh = (iu & 31) * 2;
                *(uint4*)(H1w[nxt] + m * 144 + jh * 2) = pf[q];
            }
        }

        // ---- epilogue: write h2(t) into H2[nxt]; FC on last step ----
#pragma unroll
        for (int p = 0; p < 2; p++) {
            const int js = nw * 16 + p * 8;
#pragma unroll
            for (int mt = 0; mt < 2; mt++)
#pragma unroll
            for (int rr = 0; rr < 2; rr++) {
                float hv[2];
#pragma unroll
                for (int jj = 0; jj < 2; jj++) {
                    int reg = rr * 2 + jj;
                    float gi = d[p][mt][0][reg];
                    float gf = d[p][mt][1][reg];
                    float gg = d[p][mt][2][reg];
                    float go = d[p][mt][3][reg];
                    int ci = ((p * 2 + mt) * 2 + rr) * 2 + jj;
                    float cc = sigf(gf) * c[ci] + sigf(gi) * tanha(gg);
                    c[ci] = cc;
                    hv[jj] = sigf(go) * tanha(cc);
                }
                int r = m0 + 16 * mt + (l >> 2) + 8 * rr;
                int j0 = js + 2 * (l & 3);
                *(__half2*)(H2w[nxt] + r * 144 + j0 * 2) =
                    __halves2half2(__float2half(hv[0]), __float2half(hv[1]));
                if (t == T_STEPS - 1)
                    atomicAdd(scr + r, hv[0] * wfcp[j0] + hv[1] * wfcp[j0 + 1]);
            }
        }
        __syncthreads();
    }

    if (tid < 64) out[gb + tid] = scr[tid] + bfc[0];
}

extern "C" void kernel_launch(void* const* d_in, const int* in_sizes, int n_in,
                              void* d_out, int out_size)
{
    const float* x    = (const float*)d_in[0];
    const float* Wih0 = (const float*)d_in[1];
    const float* Whh0 = (const float*)d_in[2];
    const float* bih0 = (const float*)d_in[3];
    const float* bhh0 = (const float*)d_in[4];
    const float* Wih1 = (const float*)d_in[5];
    const float* Whh1 = (const float*)d_in[6];
    const float* bih1 = (const float*)d_in[7];
    const float* bhh1 = (const float*)d_in[8];
    const float* Wfc  = (const float*)d_in[9];
    const float* bfc  = (const float*)d_in[10];
    float* out = (float*)d_out;

    cudaFuncSetAttribute(lstm_l1, cudaFuncAttributeMaxDynamicSharedMemorySize, K1_SMEM);
    cudaFuncSetAttribute(lstm_l2, cudaFuncAttributeMaxDynamicSharedMemorySize, K2_SMEM);

    lstm_l1<<<NBLK, THREADS, K1_SMEM>>>(x, Wih0, Whh0, bih0, bhh0);
    lstm_l2<<<NBLK, THREADS, K2_SMEM>>>(Wih1, Whh1, bih1, bhh1, Wfc, bfc, out);
}